// round 7
// baseline (speedup 1.0000x reference)
#include <cuda_runtime.h>
#include <math.h>

#define NMAX 50000
#define EMAX 600000
#define NGRAPH 256
#define HD 128

// ---------------- device scratch (no allocations allowed) ----------------
__device__ __align__(16) int   g_deg[NMAX];
__device__ __align__(16) float g_dinv[NMAX];
__device__ __align__(16) int   g_rowptr[NMAX];
__device__ __align__(16) int   g_cursor[NMAX];
__device__ __align__(16) int   g_col[EMAX];
__device__ __align__(16) float g_w[EMAX];
__device__ __align__(16) float g_h[NMAX * HD];   // current node features
__device__ __align__(16) float g_t[NMAX * HD];   // temp (GEMM output, pre-aggregation)
__device__ __align__(16) float g_gate[NMAX];
__device__ __align__(16) float g_stats[512];     // [0:128) sum, [128:256) sumsq, [256:384) a, [384:512) c
__device__ __align__(16) float g_stats2[256];    // pooled BN a,c
__device__ __align__(16) float g_pool[NGRAPH * HD];
__device__ __align__(16) float g_g2[NGRAPH * HD];
__device__ __align__(16) int   g_part[128];      // scan partials

// ---------------- graph structure build ----------------
__global__ void k_zero_deg(int N) {
    int i = blockIdx.x * blockDim.x + threadIdx.x;
    if (i < N) g_deg[i] = 0;
}

// edge_index is int32 (JAX x64 disabled: jnp.int64 silently becomes int32)
__global__ void k_deg(const int* __restrict__ eidx, int E) {
    int e = blockIdx.x * blockDim.x + threadIdx.x;
    if (e < E) atomicAdd(&g_deg[eidx[E + e]], 1);
}

// per-1024-chunk sums
__global__ void k_scan1(int N) {
    __shared__ int sh[256];
    int t = threadIdx.x;
    int base = blockIdx.x * 1024;
    int s = 0;
    #pragma unroll
    for (int j = 0; j < 4; j++) {
        int i = base + t + j * 256;
        if (i < N) s += g_deg[i];
    }
    sh[t] = s; __syncthreads();
    for (int off = 128; off > 0; off >>= 1) {
        if (t < off) sh[t] += sh[t + off];
        __syncthreads();
    }
    if (t == 0) g_part[blockIdx.x] = sh[0];
}

__global__ void k_scan2(int NB) {
    if (threadIdx.x == 0 && blockIdx.x == 0) {
        int acc = 0;
        for (int i = 0; i < NB; i++) { int v = g_part[i]; g_part[i] = acc; acc += v; }
    }
}

__global__ void k_scan3(int N) {
    __shared__ int sh[1024];
    int t = threadIdx.x;
    int i = blockIdx.x * 1024 + t;
    int v = (i < N) ? g_deg[i] : 0;
    sh[t] = v; __syncthreads();
    for (int off = 1; off < 1024; off <<= 1) {
        int x = (t >= off) ? sh[t - off] : 0;
        __syncthreads();
        sh[t] += x;
        __syncthreads();
    }
    if (i < N) {
        int excl = sh[t] - v;
        int start = g_part[blockIdx.x] + excl;
        g_rowptr[i] = start;
        g_cursor[i] = start;
        g_dinv[i] = rsqrtf((float)v + 1.0f);
    }
}

__global__ void k_scatter(const int* __restrict__ eidx, int E) {
    int e = blockIdx.x * blockDim.x + threadIdx.x;
    if (e < E) {
        int src = eidx[e];
        int dst = eidx[E + e];
        int pos = atomicAdd(&g_cursor[dst], 1);
        g_col[pos] = src;
        g_w[pos] = g_dinv[src] * g_dinv[dst];
    }
}

// ---------------- BatchNorm statistics ----------------
__global__ void k_zero_stats() { g_stats[threadIdx.x] = 0.f; }  // <<<1,256>>>

__global__ void k_colstats(const float* __restrict__ Aext, int sel, int N) {
    const float* __restrict__ X = sel ? (const float*)g_h : Aext;
    int col = threadIdx.x;  // 128
    float s = 0.f, s2 = 0.f;
    for (int r = blockIdx.x; r < N; r += gridDim.x) {
        float v = X[(size_t)r * HD + col];
        s += v; s2 += v * v;
    }
    atomicAdd(&g_stats[col], s);
    atomicAdd(&g_stats[128 + col], s2);
}

__global__ void k_bnfinal(const float* __restrict__ gamma, const float* __restrict__ beta, float invN) {
    int c = threadIdx.x;
    float mean = g_stats[c] * invN;
    float var  = g_stats[128 + c] * invN - mean * mean;
    float a = gamma[c] * rsqrtf(var + 1e-5f);
    g_stats[256 + c] = a;
    g_stats[384 + c] = beta[c] - mean * a;
}

// ---------------- GEMM: out[M,128] = BN(A)[M,128] @ W[128,128] ----------------
// mode 0: write g_t. mode 1 (gate): hidden=relu(acc+b1), gate=sigmoid(hidden.W2+b2) -> g_gate
__global__ __launch_bounds__(256) void k_gemm(
    const float* __restrict__ Aext, int sel, const float* __restrict__ W,
    int use_bn, int mode, int M,
    const float* __restrict__ gb1, const float* __restrict__ gW2,
    const float* __restrict__ gb2)
{
    __shared__ __align__(16) float Ws[32 * 128];
    __shared__ __align__(16) float As[32 * 68];
    __shared__ float bna[128], bnc[128], b1s[128], w2s[128];

    const float* __restrict__ A = sel ? (const float*)g_h : Aext;

    int tid = threadIdx.x;
    if (tid < 128) {
        bna[tid] = use_bn ? g_stats[256 + tid] : 1.f;
        bnc[tid] = use_bn ? g_stats[384 + tid] : 0.f;
        if (mode) { b1s[tid] = gb1[tid]; w2s[tid] = gW2[tid]; }
    }
    int rowbase = blockIdx.x * 64;
    int lane = tid & 31, warp = tid >> 5;
    float acc[8][4];
    #pragma unroll
    for (int r = 0; r < 8; r++)
        #pragma unroll
        for (int c = 0; c < 4; c++) acc[r][c] = 0.f;

    for (int k0 = 0; k0 < 128; k0 += 32) {
        __syncthreads();
        // stage W chunk [k0..k0+32) x 128
        #pragma unroll
        for (int j = 0; j < 4; j++) {
            int i = tid + j * 256;
            ((float4*)Ws)[i] = ((const float4*)(W + k0 * 128))[i];
        }
        // stage A chunk transposed [kk][row] with BN fused
        #pragma unroll
        for (int j = 0; j < 2; j++) {
            int idx = tid + j * 256;
            int r = idx >> 3, kq = idx & 7;
            int gr = rowbase + r;
            float4 v = make_float4(0.f, 0.f, 0.f, 0.f);
            if (gr < M) v = *(const float4*)(A + (size_t)gr * HD + k0 + kq * 4);
            int c0 = k0 + kq * 4;
            As[(kq * 4 + 0) * 68 + r] = v.x * bna[c0 + 0] + bnc[c0 + 0];
            As[(kq * 4 + 1) * 68 + r] = v.y * bna[c0 + 1] + bnc[c0 + 1];
            As[(kq * 4 + 2) * 68 + r] = v.z * bna[c0 + 2] + bnc[c0 + 2];
            As[(kq * 4 + 3) * 68 + r] = v.w * bna[c0 + 3] + bnc[c0 + 3];
        }
        __syncthreads();
        #pragma unroll
        for (int kk = 0; kk < 32; kk++) {
            float a0x = As[kk * 68 + warp * 8 + 0];
            float a0y = As[kk * 68 + warp * 8 + 1];
            float a0z = As[kk * 68 + warp * 8 + 2];
            float a0w = As[kk * 68 + warp * 8 + 3];
            float a1x = As[kk * 68 + warp * 8 + 4];
            float a1y = As[kk * 68 + warp * 8 + 5];
            float a1z = As[kk * 68 + warp * 8 + 6];
            float a1w = As[kk * 68 + warp * 8 + 7];
            float4 w4 = *(float4*)&Ws[kk * 128 + lane * 4];
            float av[8] = {a0x, a0y, a0z, a0w, a1x, a1y, a1z, a1w};
            float wv[4] = {w4.x, w4.y, w4.z, w4.w};
            #pragma unroll
            for (int r = 0; r < 8; r++)
                #pragma unroll
                for (int c = 0; c < 4; c++)
                    acc[r][c] += av[r] * wv[c];
        }
    }

    if (mode == 0) {
        #pragma unroll
        for (int r = 0; r < 8; r++) {
            int row = rowbase + warp * 8 + r;
            if (row < M) {
                float4 o = make_float4(acc[r][0], acc[r][1], acc[r][2], acc[r][3]);
                *(float4*)(g_t + (size_t)row * HD + lane * 4) = o;
            }
        }
    } else {
        float part[8];
        #pragma unroll
        for (int r = 0; r < 8; r++) {
            float s = 0.f;
            #pragma unroll
            for (int c = 0; c < 4; c++) {
                float h = fmaxf(acc[r][c] + b1s[lane * 4 + c], 0.f);
                s += h * w2s[lane * 4 + c];
            }
            part[r] = s;
        }
        #pragma unroll
        for (int o = 16; o; o >>= 1)
            #pragma unroll
            for (int r = 0; r < 8; r++)
                part[r] += __shfl_xor_sync(0xffffffffu, part[r], o);
        if (lane < 8) {
            int row = rowbase + warp * 8 + lane;
            if (row < M) {
                float z = part[lane] + gb2[0];
                g_gate[row] = 1.f / (1.f + expf(-z));
            }
        }
    }
}

// ---------------- SpMM aggregation: g_h = relu(A_hat * g_t + bias) ----------------
__global__ void k_spmm(const float* __restrict__ bias, int N) {
    int gw = (blockIdx.x * blockDim.x + threadIdx.x) >> 5;
    int lane = threadIdx.x & 31;
    if (gw >= N) return;
    int v = gw;
    const int*   __restrict__ colp = (const int*)g_col;
    const float* __restrict__ wp   = (const float*)g_w;
    int p = g_rowptr[v];
    int e = p + g_deg[v];
    const float4* __restrict__ H4 = (const float4*)g_t;
    float4 acc = make_float4(0.f, 0.f, 0.f, 0.f);
    for (; p + 1 < e; p += 2) {
        int s0 = colp[p], s1 = colp[p + 1];
        float w0 = wp[p], w1 = wp[p + 1];
        float4 h0 = H4[(size_t)s0 * 32 + lane];
        float4 h1 = H4[(size_t)s1 * 32 + lane];
        acc.x += w0 * h0.x + w1 * h1.x;
        acc.y += w0 * h0.y + w1 * h1.y;
        acc.z += w0 * h0.z + w1 * h1.z;
        acc.w += w0 * h0.w + w1 * h1.w;
    }
    if (p < e) {
        int s0 = colp[p]; float w0 = wp[p];
        float4 h0 = H4[(size_t)s0 * 32 + lane];
        acc.x += w0 * h0.x; acc.y += w0 * h0.y; acc.z += w0 * h0.z; acc.w += w0 * h0.w;
    }
    float di = g_dinv[v];
    float ws = di * di;
    float4 hs = H4[(size_t)v * 32 + lane];
    float4 b = ((const float4*)bias)[lane];
    acc.x = fmaxf(acc.x + ws * hs.x + b.x, 0.f);
    acc.y = fmaxf(acc.y + ws * hs.y + b.y, 0.f);
    acc.z = fmaxf(acc.z + ws * hs.z + b.z, 0.f);
    acc.w = fmaxf(acc.w + ws * hs.w + b.w, 0.f);
    ((float4*)g_h)[(size_t)v * 32 + lane] = acc;
}

// ---------------- gated pooling (batch is sorted int32 -> segmented, no atomics) ----------------
__device__ __forceinline__ int lower_bound_i32(const int* a, int n, int key) {
    int lo = 0, hi = n;
    while (lo < hi) { int mid = (lo + hi) >> 1; if (a[mid] < key) lo = mid + 1; else hi = mid; }
    return lo;
}

__global__ void k_pool(const int* __restrict__ batch, int N) {
    int g = blockIdx.x;         // 256
    int col = threadIdx.x;      // 128
    int start = lower_bound_i32(batch, N, g);
    int end   = lower_bound_i32(batch, N, g + 1);
    float s = 0.f;
    for (int r = start; r < end; r++)
        s += g_h[(size_t)r * HD + col] * g_gate[r];
    g_pool[g * HD + col] = s;
}

__global__ void k_bnpool(const float* __restrict__ gamma, const float* __restrict__ beta) {
    int c = threadIdx.x;  // 128
    float s = 0.f, s2 = 0.f;
    for (int r = 0; r < NGRAPH; r++) {
        float v = g_pool[r * HD + c];
        s += v; s2 += v * v;
    }
    float invG = 1.f / (float)NGRAPH;
    float mean = s * invG;
    float var  = s2 * invG - mean * mean;
    float a = gamma[c] * rsqrtf(var + 1e-5f);
    g_stats2[c] = a;
    g_stats2[128 + c] = beta[c] - mean * a;
}

__global__ void k_fc(const float* __restrict__ fcW, const float* __restrict__ fcb) {
    int g = blockIdx.x, t = threadIdx.x;  // 256 x 128
    __shared__ float srow[128];
    srow[t] = g_pool[g * HD + t] * g_stats2[t] + g_stats2[128 + t];
    __syncthreads();
    float acc = fcb[t];
    #pragma unroll
    for (int k = 0; k < 128; k++)
        acc += srow[k] * fcW[k * 128 + t];
    g_g2[g * HD + t] = fmaxf(acc, 0.f);
}

__global__ void k_cls(const float* __restrict__ clsW, const float* __restrict__ clsb,
                      float* __restrict__ out) {
    int g = blockIdx.x, t = threadIdx.x;  // 256 x 32
    __shared__ float srow[128];
    __shared__ float lg[10];
    __shared__ float s_lse;
    for (int i = t; i < 128; i += 32) srow[i] = g_g2[g * HD + i];
    __syncthreads();
    if (t < 10) {
        float a = clsb[t];
        #pragma unroll
        for (int k = 0; k < 128; k++) a += srow[k] * clsW[k * 10 + t];
        lg[t] = a;
    }
    __syncthreads();
    if (t == 0) {
        float m = lg[0];
        #pragma unroll
        for (int i = 1; i < 10; i++) m = fmaxf(m, lg[i]);
        float s = 0.f;
        #pragma unroll
        for (int i = 0; i < 10; i++) s += expf(lg[i] - m);
        s_lse = m + logf(s);
    }
    __syncthreads();
    if (t < 10) out[g * 10 + t] = lg[t] - s_lse;
}

// ---------------- launch ----------------
extern "C" void kernel_launch(void* const* d_in, const int* in_sizes, int n_in,
                              void* d_out, int out_size) {
    const float* x           = (const float*)d_in[0];
    const int*   eidx        = (const int*)d_in[1];    // int32! (JAX x64 disabled)
    const int*   batch       = (const int*)d_in[2];    // int32!
    const float* bn_feat_g   = (const float*)d_in[3];
    const float* bn_feat_b   = (const float*)d_in[4];
    const float* conv_feat_W = (const float*)d_in[5];
    const float* conv_feat_b = (const float*)d_in[6];
    const float* conv_W      = (const float*)d_in[7];
    const float* conv_b      = (const float*)d_in[8];
    const float* bn_conv_g   = (const float*)d_in[9];
    const float* bn_conv_b   = (const float*)d_in[10];
    const float* gate_W1     = (const float*)d_in[11];
    const float* gate_b1     = (const float*)d_in[12];
    const float* gate_W2     = (const float*)d_in[13];
    const float* gate_b2     = (const float*)d_in[14];
    const float* fc_W        = (const float*)d_in[15];
    const float* fc_b        = (const float*)d_in[16];
    const float* bn_fc_g     = (const float*)d_in[17];
    const float* bn_fc_b     = (const float*)d_in[18];
    const float* cls_W       = (const float*)d_in[19];
    const float* cls_b       = (const float*)d_in[20];
    float* out = (float*)d_out;

    int N = in_sizes[0] / HD;
    int E = in_sizes[1] / 2;
    int NB = (N + 1023) >> 10;
    int EB = (E + 255) / 256;
    int GB = (N + 63) / 64;
    float invN = 1.f / (float)N;

    // graph structure (CSR by counting sort)
    k_zero_deg<<<(N + 255) / 256, 256>>>(N);
    k_deg<<<EB, 256>>>(eidx, E);
    k_scan1<<<NB, 256>>>(N);
    k_scan2<<<1, 32>>>(NB);
    k_scan3<<<NB, 1024>>>(N);
    k_scatter<<<EB, 256>>>(eidx, E);

    // layer 0: BN(x) -> GEMM -> aggregate+relu
    k_zero_stats<<<1, 256>>>();
    k_colstats<<<256, 128>>>(x, 0, N);
    k_bnfinal<<<1, 128>>>(bn_feat_g, bn_feat_b, invN);
    k_gemm<<<GB, 256>>>(x, 0, conv_feat_W, 1, 0, N, nullptr, nullptr, nullptr);
    k_spmm<<<(N + 7) / 8, 256>>>(conv_feat_b, N);

    // conv layers 1..3
    for (int i = 0; i < 3; i++) {
        k_zero_stats<<<1, 256>>>();
        k_colstats<<<256, 128>>>(nullptr, 1, N);
        k_bnfinal<<<1, 128>>>(bn_conv_g + i * 128, bn_conv_b + i * 128, invN);
        k_gemm<<<GB, 256>>>(nullptr, 1, conv_W + i * 128 * 128, 1, 0, N, nullptr, nullptr, nullptr);
        k_spmm<<<(N + 7) / 8, 256>>>(conv_b + i * 128, N);
    }

    // gate (fused GEMM + relu + dot W2 + sigmoid)
    k_gemm<<<GB, 256>>>(nullptr, 1, gate_W1, 0, 1, N, gate_b1, gate_W2, gate_b2);

    // pooling + head
    k_pool<<<NGRAPH, 128>>>(batch, N);
    k_bnpool<<<1, 128>>>(bn_fc_g, bn_fc_b);
    k_fc<<<NGRAPH, 128>>>(fc_W, fc_b);
    k_cls<<<NGRAPH, 32>>>(cls_W, cls_b, out);
}

// round 8
// speedup vs baseline: 1.2455x; 1.2455x over previous
#include <cuda_runtime.h>
#include <math.h>
#include <stdint.h>

#define NMAX 50000
#define EMAX 600000
#define NGRAPH 256
#define HD 128

// ---------------- device scratch (no allocations allowed) ----------------
__device__ __align__(16) int   g_deg[NMAX];
__device__ __align__(16) float g_dinv[NMAX];
__device__ __align__(16) int   g_rowptr[NMAX];
__device__ __align__(16) int   g_cursor[NMAX];
__device__ __align__(16) int   g_col[EMAX];
__device__ __align__(16) float g_w[EMAX];
__device__ __align__(16) float g_h[NMAX * HD];
__device__ __align__(16) float g_t[NMAX * HD];
__device__ __align__(16) float g_gate[NMAX];
__device__ __align__(16) float g_stats[512];   // sum | sumsq | a | c
__device__ __align__(16) float g_stats2[256];
__device__ __align__(16) float g_pool[NGRAPH * HD];
__device__ __align__(16) float g_g2[NGRAPH * HD];
__device__ __align__(16) int   g_part[128];

// ---------------- graph structure build ----------------
__global__ void k_zero_deg(int N) {
    int i = blockIdx.x * blockDim.x + threadIdx.x;
    if (i < N) g_deg[i] = 0;
}

__global__ void k_deg(const int* __restrict__ eidx, int E) {
    int e = blockIdx.x * blockDim.x + threadIdx.x;
    if (e < E) atomicAdd(&g_deg[eidx[E + e]], 1);
}

__global__ void k_scan1(int N) {
    __shared__ int sh[256];
    int t = threadIdx.x;
    int base = blockIdx.x * 1024;
    int s = 0;
    #pragma unroll
    for (int j = 0; j < 4; j++) {
        int i = base + t + j * 256;
        if (i < N) s += g_deg[i];
    }
    sh[t] = s; __syncthreads();
    for (int off = 128; off > 0; off >>= 1) {
        if (t < off) sh[t] += sh[t + off];
        __syncthreads();
    }
    if (t == 0) g_part[blockIdx.x] = sh[0];
}

__global__ void k_scan2(int NB) {   // <<<1,64>>> parallel exclusive scan of partials
    __shared__ int sh[64];
    int t = threadIdx.x;
    int v = (t < NB) ? g_part[t] : 0;
    sh[t] = v; __syncthreads();
    for (int off = 1; off < 64; off <<= 1) {
        int x = (t >= off) ? sh[t - off] : 0;
        __syncthreads();
        sh[t] += x;
        __syncthreads();
    }
    if (t < NB) g_part[t] = sh[t] - v;
}

__global__ void k_scan3(int N) {
    __shared__ int sh[1024];
    int t = threadIdx.x;
    int i = blockIdx.x * 1024 + t;
    int v = (i < N) ? g_deg[i] : 0;
    sh[t] = v; __syncthreads();
    for (int off = 1; off < 1024; off <<= 1) {
        int x = (t >= off) ? sh[t - off] : 0;
        __syncthreads();
        sh[t] += x;
        __syncthreads();
    }
    if (i < N) {
        int excl = sh[t] - v;
        int start = g_part[blockIdx.x] + excl;
        g_rowptr[i] = start;
        g_cursor[i] = start;
        g_dinv[i] = rsqrtf((float)v + 1.0f);
    }
}

__global__ void k_scatter(const int* __restrict__ eidx, int E) {
    int e = blockIdx.x * blockDim.x + threadIdx.x;
    if (e < E) {
        int src = eidx[e];
        int dst = eidx[E + e];
        int pos = atomicAdd(&g_cursor[dst], 1);
        g_col[pos] = src;
        g_w[pos] = g_dinv[src] * g_dinv[dst];
    }
}

// ---------------- BatchNorm statistics ----------------
__global__ void k_zero_stats() { g_stats[threadIdx.x] = 0.f; }  // <<<1,256>>>

__global__ void k_colstats(const float* __restrict__ Aext, int sel, int N) {
    const float* __restrict__ X = sel ? (const float*)g_h : Aext;
    int col = threadIdx.x;  // 128
    float s = 0.f, s2 = 0.f;
    for (int r = blockIdx.x; r < N; r += gridDim.x) {
        float v = X[(size_t)r * HD + col];
        s += v; s2 += v * v;
    }
    atomicAdd(&g_stats[col], s);
    atomicAdd(&g_stats[128 + col], s2);
}

__global__ void k_bnfinal(const float* __restrict__ gamma, const float* __restrict__ beta, float invN) {
    int c = threadIdx.x;
    float mean = g_stats[c] * invN;
    float var  = g_stats[128 + c] * invN - mean * mean;
    float a = gamma[c] * rsqrtf(var + 1e-5f);
    g_stats[256 + c] = a;
    g_stats[384 + c] = beta[c] - mean * a;
}

// ---------------- tensor-core GEMM (3xTF32 split, fp32-accurate) ----------------
__device__ __forceinline__ uint32_t f2tf32(float x) {
    uint32_t r;
    asm("cvt.rna.tf32.f32 %0, %1;" : "=r"(r) : "f"(x));
    return r;
}
__device__ __forceinline__ void split_tf32(float x, uint32_t& hi, uint32_t& lo) {
    hi = f2tf32(x);
    lo = f2tf32(x - __uint_as_float(hi));
}
__device__ __forceinline__ void mma_tf32(float* c, const uint32_t* a, uint32_t b0, uint32_t b1) {
    asm volatile(
        "mma.sync.aligned.m16n8k8.row.col.f32.tf32.tf32.f32 "
        "{%0,%1,%2,%3}, {%4,%5,%6,%7}, {%8,%9}, {%0,%1,%2,%3};"
        : "+f"(c[0]), "+f"(c[1]), "+f"(c[2]), "+f"(c[3])
        : "r"(a[0]), "r"(a[1]), "r"(a[2]), "r"(a[3]), "r"(b0), "r"(b1));
}

#define SW_STRIDE 136   // (136 mod 32)=8 -> B-frag LDS conflict-free
#define SA_STRIDE 36    // (36 mod 32)=4  -> A-frag LDS conflict-free
// dynamic smem layout (floats): sW[128*136] | sA[128*36] | bna[128] bnc[128] b1s[128] w2s[128]
#define SMEM_FLOATS (128 * SW_STRIDE + 128 * SA_STRIDE + 512)

// out[M,128] = BN(A)[M,128] @ W[128,128]; mode0 -> g_t, mode1 -> gate scalar
__global__ __launch_bounds__(256) void k_gemm_tc(
    const float* __restrict__ Aext, int sel, const float* __restrict__ W,
    int use_bn, int mode, int M,
    const float* __restrict__ gb1, const float* __restrict__ gW2,
    const float* __restrict__ gb2)
{
    extern __shared__ float sm[];
    float* sW  = sm;
    float* sA  = sm + 128 * SW_STRIDE;
    float* bna = sA + 128 * SA_STRIDE;
    float* bnc = bna + 128;
    float* b1s = bnc + 128;
    float* w2s = b1s + 128;

    const float* __restrict__ A = sel ? (const float*)g_h : Aext;
    int tid = threadIdx.x;

    if (tid < 128) {
        bna[tid] = use_bn ? g_stats[256 + tid] : 1.f;
        bnc[tid] = use_bn ? g_stats[384 + tid] : 0.f;
        b1s[tid] = mode ? gb1[tid] : 0.f;
        w2s[tid] = mode ? gW2[tid] : 0.f;
    }
    // stage whole W [k][n] (row k, col n)
    for (int i = tid; i < 128 * 32; i += 256) {
        int k = i >> 5, n4 = i & 31;
        float4 v = ((const float4*)W)[i];
        float* dst = &sW[k * SW_STRIDE + n4 * 4];
        dst[0] = v.x; dst[1] = v.y; dst[2] = v.z; dst[3] = v.w;
    }

    int rowbase = blockIdx.x * 128;
    int warp = tid >> 5, lane = tid & 31;
    int g = lane >> 2, t = lane & 3;
    int wm = warp >> 1, wn = warp & 1;
    int mbase = wm * 32;
    int nbase = wn * 64;

    float acc[2][8][4];
    #pragma unroll
    for (int i = 0; i < 2; i++)
        #pragma unroll
        for (int j = 0; j < 8; j++)
            #pragma unroll
            for (int c = 0; c < 4; c++) acc[i][j][c] = 0.f;

    for (int k0 = 0; k0 < 128; k0 += 32) {
        __syncthreads();
        // stage A chunk [128 rows][32 k] with BN fused
        for (int i = tid; i < 128 * 8; i += 256) {
            int r = i >> 3, kq = i & 7;
            int gr = rowbase + r;
            float4 v = make_float4(0.f, 0.f, 0.f, 0.f);
            if (gr < M) v = *(const float4*)(A + (size_t)gr * HD + k0 + kq * 4);
            int c0 = k0 + kq * 4;
            float* dst = &sA[r * SA_STRIDE + kq * 4];
            dst[0] = v.x * bna[c0 + 0] + bnc[c0 + 0];
            dst[1] = v.y * bna[c0 + 1] + bnc[c0 + 1];
            dst[2] = v.z * bna[c0 + 2] + bnc[c0 + 2];
            dst[3] = v.w * bna[c0 + 3] + bnc[c0 + 3];
        }
        __syncthreads();
        #pragma unroll
        for (int ks = 0; ks < 32; ks += 8) {
            // A fragments (m16k8): a0:(g,t) a1:(g+8,t) a2:(g,t+4) a3:(g+8,t+4)
            uint32_t ahi[2][4], alo[2][4];
            #pragma unroll
            for (int i = 0; i < 2; i++) {
                int r0 = mbase + i * 16 + g;
                float f0 = sA[r0 * SA_STRIDE + ks + t];
                float f1 = sA[(r0 + 8) * SA_STRIDE + ks + t];
                float f2 = sA[r0 * SA_STRIDE + ks + t + 4];
                float f3 = sA[(r0 + 8) * SA_STRIDE + ks + t + 4];
                split_tf32(f0, ahi[i][0], alo[i][0]);
                split_tf32(f1, ahi[i][1], alo[i][1]);
                split_tf32(f2, ahi[i][2], alo[i][2]);
                split_tf32(f3, ahi[i][3], alo[i][3]);
            }
            #pragma unroll
            for (int j = 0; j < 8; j++) {
                // B fragment (k8n8): b0:(k=t, n=g) b1:(k=t+4, n=g)
                int n = nbase + j * 8 + g;
                float f0 = sW[(k0 + ks + t) * SW_STRIDE + n];
                float f1 = sW[(k0 + ks + t + 4) * SW_STRIDE + n];
                uint32_t bh0, bl0, bh1, bl1;
                split_tf32(f0, bh0, bl0);
                split_tf32(f1, bh1, bl1);
                #pragma unroll
                for (int i = 0; i < 2; i++) {
                    mma_tf32(acc[i][j], ahi[i], bh0, bh1);   // hi*hi
                    mma_tf32(acc[i][j], ahi[i], bl0, bl1);   // hi*lo
                    mma_tf32(acc[i][j], alo[i], bh0, bh1);   // lo*hi
                }
            }
        }
    }

    if (mode == 0) {
        // C frag (m16n8): c0:(g,2t) c1:(g,2t+1) c2:(g+8,2t) c3:(g+8,2t+1)
        #pragma unroll
        for (int i = 0; i < 2; i++) {
            int r  = rowbase + mbase + i * 16 + g;
            int r8 = r + 8;
            #pragma unroll
            for (int j = 0; j < 8; j++) {
                int col = nbase + j * 8 + 2 * t;
                if (r < M)
                    *(float2*)(g_t + (size_t)r * HD + col) = make_float2(acc[i][j][0], acc[i][j][1]);
                if (r8 < M)
                    *(float2*)(g_t + (size_t)r8 * HD + col) = make_float2(acc[i][j][2], acc[i][j][3]);
            }
        }
    } else {
        // gate: per-row sum over cols of relu(acc+b1)*w2, then sigmoid(sum+b2)
        __syncthreads();           // sA no longer needed; reuse as rsum[128][2]
        float* rsum = sA;
        #pragma unroll
        for (int i = 0; i < 2; i++) {
            float s0 = 0.f, s1 = 0.f;
            #pragma unroll
            for (int j = 0; j < 8; j++) {
                int col = nbase + j * 8 + 2 * t;
                s0 += fmaxf(acc[i][j][0] + b1s[col], 0.f)     * w2s[col];
                s0 += fmaxf(acc[i][j][1] + b1s[col + 1], 0.f) * w2s[col + 1];
                s1 += fmaxf(acc[i][j][2] + b1s[col], 0.f)     * w2s[col];
                s1 += fmaxf(acc[i][j][3] + b1s[col + 1], 0.f) * w2s[col + 1];
            }
            s0 += __shfl_xor_sync(0xffffffffu, s0, 1);
            s0 += __shfl_xor_sync(0xffffffffu, s0, 2);
            s1 += __shfl_xor_sync(0xffffffffu, s1, 1);
            s1 += __shfl_xor_sync(0xffffffffu, s1, 2);
            if (t == 0) {
                int lr  = mbase + i * 16 + g;       // 0..127 local row
                rsum[lr * 2 + wn]       = s0;
                rsum[(lr + 8) * 2 + wn] = s1;
            }
        }
        __syncthreads();
        if (tid < 128) {
            int row = rowbase + tid;
            if (row < M) {
                float z = rsum[tid * 2] + rsum[tid * 2 + 1] + gb2[0];
                g_gate[row] = 1.f / (1.f + expf(-z));
            }
        }
    }
}

// ---------------- SpMM aggregation: g_h = relu(A_hat * g_t + bias) ----------------
__global__ void k_spmm(const float* __restrict__ bias, int N) {
    int gw = (blockIdx.x * blockDim.x + threadIdx.x) >> 5;
    int lane = threadIdx.x & 31;
    if (gw >= N) return;
    int v = gw;
    const int*   __restrict__ colp = (const int*)g_col;
    const float* __restrict__ wp   = (const float*)g_w;
    int p = g_rowptr[v];
    int e = p + g_deg[v];
    const float4* __restrict__ H4 = (const float4*)g_t;
    float4 acc = make_float4(0.f, 0.f, 0.f, 0.f);
    for (; p + 3 < e; p += 4) {
        int s0 = colp[p], s1 = colp[p + 1], s2 = colp[p + 2], s3 = colp[p + 3];
        float w0 = wp[p], w1 = wp[p + 1], w2 = wp[p + 2], w3 = wp[p + 3];
        float4 h0 = H4[(size_t)s0 * 32 + lane];
        float4 h1 = H4[(size_t)s1 * 32 + lane];
        float4 h2 = H4[(size_t)s2 * 32 + lane];
        float4 h3 = H4[(size_t)s3 * 32 + lane];
        acc.x += w0 * h0.x + w1 * h1.x + w2 * h2.x + w3 * h3.x;
        acc.y += w0 * h0.y + w1 * h1.y + w2 * h2.y + w3 * h3.y;
        acc.z += w0 * h0.z + w1 * h1.z + w2 * h2.z + w3 * h3.z;
        acc.w += w0 * h0.w + w1 * h1.w + w2 * h2.w + w3 * h3.w;
    }
    for (; p < e; p++) {
        int s0 = colp[p]; float w0 = wp[p];
        float4 h0 = H4[(size_t)s0 * 32 + lane];
        acc.x += w0 * h0.x; acc.y += w0 * h0.y; acc.z += w0 * h0.z; acc.w += w0 * h0.w;
    }
    float di = g_dinv[v];
    float ws = di * di;
    float4 hs = H4[(size_t)v * 32 + lane];
    float4 b = ((const float4*)bias)[lane];
    acc.x = fmaxf(acc.x + ws * hs.x + b.x, 0.f);
    acc.y = fmaxf(acc.y + ws * hs.y + b.y, 0.f);
    acc.z = fmaxf(acc.z + ws * hs.z + b.z, 0.f);
    acc.w = fmaxf(acc.w + ws * hs.w + b.w, 0.f);
    ((float4*)g_h)[(size_t)v * 32 + lane] = acc;
}

// ---------------- gated pooling ----------------
__device__ __forceinline__ int lower_bound_i32(const int* a, int n, int key) {
    int lo = 0, hi = n;
    while (lo < hi) { int mid = (lo + hi) >> 1; if (a[mid] < key) lo = mid + 1; else hi = mid; }
    return lo;
}

__global__ void k_pool(const int* __restrict__ batch, int N) {
    int g = blockIdx.x;
    int col = threadIdx.x;
    int start = lower_bound_i32(batch, N, g);
    int end   = lower_bound_i32(batch, N, g + 1);
    float s = 0.f;
    for (int r = start; r < end; r++)
        s += g_h[(size_t)r * HD + col] * g_gate[r];
    g_pool[g * HD + col] = s;
}

__global__ void k_bnpool(const float* __restrict__ gamma, const float* __restrict__ beta) {
    int c = threadIdx.x;
    float s = 0.f, s2 = 0.f;
    for (int r = 0; r < NGRAPH; r++) {
        float v = g_pool[r * HD + c];
        s += v; s2 += v * v;
    }
    float invG = 1.f / (float)NGRAPH;
    float mean = s * invG;
    float var  = s2 * invG - mean * mean;
    float a = gamma[c] * rsqrtf(var + 1e-5f);
    g_stats2[c] = a;
    g_stats2[128 + c] = beta[c] - mean * a;
}

__global__ void k_fc(const float* __restrict__ fcW, const float* __restrict__ fcb) {
    int g = blockIdx.x, t = threadIdx.x;
    __shared__ float srow[128];
    srow[t] = g_pool[g * HD + t] * g_stats2[t] + g_stats2[128 + t];
    __syncthreads();
    float acc = fcb[t];
    #pragma unroll
    for (int k = 0; k < 128; k++)
        acc += srow[k] * fcW[k * 128 + t];
    g_g2[g * HD + t] = fmaxf(acc, 0.f);
}

__global__ void k_cls(const float* __restrict__ clsW, const float* __restrict__ clsb,
                      float* __restrict__ out) {
    int g = blockIdx.x, t = threadIdx.x;
    __shared__ float srow[128];
    __shared__ float lg[10];
    __shared__ float s_lse;
    for (int i = t; i < 128; i += 32) srow[i] = g_g2[g * HD + i];
    __syncthreads();
    if (t < 10) {
        float a = clsb[t];
        #pragma unroll
        for (int k = 0; k < 128; k++) a += srow[k] * clsW[k * 10 + t];
        lg[t] = a;
    }
    __syncthreads();
    if (t == 0) {
        float m = lg[0];
        #pragma unroll
        for (int i = 1; i < 10; i++) m = fmaxf(m, lg[i]);
        float s = 0.f;
        #pragma unroll
        for (int i = 0; i < 10; i++) s += expf(lg[i] - m);
        s_lse = m + logf(s);
    }
    __syncthreads();
    if (t < 10) out[g * 10 + t] = lg[t] - s_lse;
}

// ---------------- launch ----------------
extern "C" void kernel_launch(void* const* d_in, const int* in_sizes, int n_in,
                              void* d_out, int out_size) {
    const float* x           = (const float*)d_in[0];
    const int*   eidx        = (const int*)d_in[1];    // int32 (JAX x64 disabled)
    const int*   batch       = (const int*)d_in[2];
    const float* bn_feat_g   = (const float*)d_in[3];
    const float* bn_feat_b   = (const float*)d_in[4];
    const float* conv_feat_W = (const float*)d_in[5];
    const float* conv_feat_b = (const float*)d_in[6];
    const float* conv_W      = (const float*)d_in[7];
    const float* conv_b      = (const float*)d_in[8];
    const float* bn_conv_g   = (const float*)d_in[9];
    const float* bn_conv_b   = (const float*)d_in[10];
    const float* gate_W1     = (const float*)d_in[11];
    const float* gate_b1     = (const float*)d_in[12];
    const float* gate_W2     = (const float*)d_in[13];
    const float* gate_b2     = (const float*)d_in[14];
    const float* fc_W        = (const float*)d_in[15];
    const float* fc_b        = (const float*)d_in[16];
    const float* bn_fc_g     = (const float*)d_in[17];
    const float* bn_fc_b     = (const float*)d_in[18];
    const float* cls_W       = (const float*)d_in[19];
    const float* cls_b       = (const float*)d_in[20];
    float* out = (float*)d_out;

    int N = in_sizes[0] / HD;
    int E = in_sizes[1] / 2;
    int NB = (N + 1023) >> 10;
    int EB = (E + 255) / 256;
    int GB = (N + 127) / 128;
    float invN = 1.f / (float)N;

    static int smem_set = 0;
    int smem_bytes = SMEM_FLOATS * 4;
    if (!smem_set) {
        cudaFuncSetAttribute(k_gemm_tc, cudaFuncAttributeMaxDynamicSharedMemorySize, smem_bytes);
        smem_set = 1;
    }

    // graph structure (CSR by counting sort)
    k_zero_deg<<<(N + 255) / 256, 256>>>(N);
    k_deg<<<EB, 256>>>(eidx, E);
    k_scan1<<<NB, 256>>>(N);
    k_scan2<<<1, 64>>>(NB);
    k_scan3<<<NB, 1024>>>(N);
    k_scatter<<<EB, 256>>>(eidx, E);

    // layer 0
    k_zero_stats<<<1, 256>>>();
    k_colstats<<<1184, 128>>>(x, 0, N);
    k_bnfinal<<<1, 128>>>(bn_feat_g, bn_feat_b, invN);
    k_gemm_tc<<<GB, 256, smem_bytes>>>(x, 0, conv_feat_W, 1, 0, N, nullptr, nullptr, nullptr);
    k_spmm<<<(N + 7) / 8, 256>>>(conv_feat_b, N);

    // conv layers 1..3
    for (int i = 0; i < 3; i++) {
        k_zero_stats<<<1, 256>>>();
        k_colstats<<<1184, 128>>>(nullptr, 1, N);
        k_bnfinal<<<1, 128>>>(bn_conv_g + i * 128, bn_conv_b + i * 128, invN);
        k_gemm_tc<<<GB, 256, smem_bytes>>>(nullptr, 1, conv_W + i * 128 * 128, 1, 0, N, nullptr, nullptr, nullptr);
        k_spmm<<<(N + 7) / 8, 256>>>(conv_b + i * 128, N);
    }

    // gate (fused GEMM + relu + dot W2 + sigmoid)
    k_gemm_tc<<<GB, 256, smem_bytes>>>(nullptr, 1, gate_W1, 0, 1, N, gate_b1, gate_W2, gate_b2);

    // pooling + head
    k_pool<<<NGRAPH, 128>>>(batch, N);
    k_bnpool<<<1, 128>>>(bn_fc_g, bn_fc_b);
    k_fc<<<NGRAPH, 128>>>(fc_W, fc_b);
    k_cls<<<NGRAPH, 32>>>(cls_W, cls_b, out);
}

// round 9
// speedup vs baseline: 1.3417x; 1.0773x over previous
#include <cuda_runtime.h>
#include <math.h>
#include <stdint.h>

#define NMAX 50000
#define EMAX 600000
#define NGRAPH 256
#define HD 128

// ---------------- device scratch (no allocations allowed) ----------------
__device__ __align__(16) int   g_deg[NMAX];
__device__ __align__(16) float g_dinv[NMAX];
__device__ __align__(16) int   g_rowptr[NMAX];
__device__ __align__(16) int   g_cursor[NMAX];
__device__ __align__(16) int   g_col[EMAX];
__device__ __align__(16) float g_w[EMAX];
__device__ __align__(16) float g_h[NMAX * HD];
__device__ __align__(16) float g_t[NMAX * HD];
__device__ __align__(16) float g_gate[NMAX];
__device__ __align__(16) float g_stats[512];   // sum | sumsq | a | c
__device__ __align__(16) float g_stats2[256];
__device__ __align__(16) float g_pool[NGRAPH * HD];
__device__ __align__(16) float g_g2[NGRAPH * HD];
__device__ __align__(16) int   g_part[128];

// ---------------- graph structure build ----------------
__global__ void k_zero_deg(int N) {
    int i = blockIdx.x * blockDim.x + threadIdx.x;
    if (i < N) g_deg[i] = 0;
}

__global__ void k_deg(const int* __restrict__ eidx, int E) {
    int e = blockIdx.x * blockDim.x + threadIdx.x;
    if (e < E) atomicAdd(&g_deg[eidx[E + e]], 1);
}

__global__ void k_scan1(int N) {
    __shared__ int sh[256];
    int t = threadIdx.x;
    int base = blockIdx.x * 1024;
    int s = 0;
    #pragma unroll
    for (int j = 0; j < 4; j++) {
        int i = base + t + j * 256;
        if (i < N) s += g_deg[i];
    }
    sh[t] = s; __syncthreads();
    for (int off = 128; off > 0; off >>= 1) {
        if (t < off) sh[t] += sh[t + off];
        __syncthreads();
    }
    if (t == 0) g_part[blockIdx.x] = sh[0];
}

__global__ void k_scan2(int NB) {   // <<<1,64>>>
    __shared__ int sh[64];
    int t = threadIdx.x;
    int v = (t < NB) ? g_part[t] : 0;
    sh[t] = v; __syncthreads();
    for (int off = 1; off < 64; off <<= 1) {
        int x = (t >= off) ? sh[t - off] : 0;
        __syncthreads();
        sh[t] += x;
        __syncthreads();
    }
    if (t < NB) g_part[t] = sh[t] - v;
}

__global__ void k_scan3(int N) {
    __shared__ int sh[1024];
    int t = threadIdx.x;
    int i = blockIdx.x * 1024 + t;
    int v = (i < N) ? g_deg[i] : 0;
    sh[t] = v; __syncthreads();
    for (int off = 1; off < 1024; off <<= 1) {
        int x = (t >= off) ? sh[t - off] : 0;
        __syncthreads();
        sh[t] += x;
        __syncthreads();
    }
    if (i < N) {
        int excl = sh[t] - v;
        int start = g_part[blockIdx.x] + excl;
        g_rowptr[i] = start;
        g_cursor[i] = start;
        g_dinv[i] = rsqrtf((float)v + 1.0f);
    }
}

__global__ void k_scatter(const int* __restrict__ eidx, int E) {
    int e = blockIdx.x * blockDim.x + threadIdx.x;
    if (e < E) {
        int src = eidx[e];
        int dst = eidx[E + e];
        int pos = atomicAdd(&g_cursor[dst], 1);
        g_col[pos] = src;
        g_w[pos] = g_dinv[src] * g_dinv[dst];
    }
}

// ---------------- BatchNorm statistics ----------------
// colstats only used for the external input x (layer 0)
__global__ void k_colstats(const float* __restrict__ X, int N) {
    int col = threadIdx.x;  // 128
    float s = 0.f, s2 = 0.f;
    for (int r = blockIdx.x; r < N; r += gridDim.x) {
        float v = X[(size_t)r * HD + col];
        s += v; s2 += v * v;
    }
    atomicAdd(&g_stats[col], s);
    atomicAdd(&g_stats[128 + col], s2);
}

// consumes sum/sumsq, produces a/c, then re-zeroes sum/sumsq (so no zero kernel needed;
// every replay starts and ends with g_stats[0:256) == 0)
__global__ void k_bnfinal(const float* __restrict__ gamma, const float* __restrict__ beta, float invN) {
    int c = threadIdx.x;
    float mean = g_stats[c] * invN;
    float var  = g_stats[128 + c] * invN - mean * mean;
    float a = gamma[c] * rsqrtf(var + 1e-5f);
    g_stats[256 + c] = a;
    g_stats[384 + c] = beta[c] - mean * a;
    g_stats[c] = 0.f;
    g_stats[128 + c] = 0.f;
}

// ---------------- tensor-core GEMM (3xTF32 split) ----------------
__device__ __forceinline__ uint32_t f2tf32(float x) {
    uint32_t r;
    asm("cvt.rna.tf32.f32 %0, %1;" : "=r"(r) : "f"(x));
    return r;
}
__device__ __forceinline__ void split_tf32(float x, uint32_t& hi, uint32_t& lo) {
    hi = f2tf32(x);
    lo = f2tf32(x - __uint_as_float(hi));
}
__device__ __forceinline__ void mma_tf32(float* c, const uint32_t* a, uint32_t b0, uint32_t b1) {
    asm volatile(
        "mma.sync.aligned.m16n8k8.row.col.f32.tf32.tf32.f32 "
        "{%0,%1,%2,%3}, {%4,%5,%6,%7}, {%8,%9}, {%0,%1,%2,%3};"
        : "+f"(c[0]), "+f"(c[1]), "+f"(c[2]), "+f"(c[3])
        : "r"(a[0]), "r"(a[1]), "r"(a[2]), "r"(a[3]), "r"(b0), "r"(b1));
}

#define SW_STRIDE 136
#define SA_STRIDE 36
// floats: sW[128*136] | sAhi[128*36] | sAlo[128*36] | bna,bnc,b1s,w2s[512]
#define SMEM_FLOATS (128 * SW_STRIDE + 2 * 128 * SA_STRIDE + 512)

__global__ __launch_bounds__(256, 2) void k_gemm_tc(
    const float* __restrict__ Aext, int sel, const float* __restrict__ W,
    int use_bn, int mode, int M,
    const float* __restrict__ gb1, const float* __restrict__ gW2,
    const float* __restrict__ gb2)
{
    extern __shared__ float sm[];
    float*    sW   = sm;
    uint32_t* sAhi = (uint32_t*)(sm + 128 * SW_STRIDE);
    uint32_t* sAlo = sAhi + 128 * SA_STRIDE;
    float*    bna  = (float*)(sAlo + 128 * SA_STRIDE);
    float*    bnc  = bna + 128;
    float*    b1s  = bnc + 128;
    float*    w2s  = b1s + 128;

    const float* __restrict__ A = sel ? (const float*)g_h : Aext;
    int tid = threadIdx.x;

    if (tid < 128) {
        bna[tid] = use_bn ? g_stats[256 + tid] : 1.f;
        bnc[tid] = use_bn ? g_stats[384 + tid] : 0.f;
        b1s[tid] = mode ? gb1[tid] : 0.f;
        w2s[tid] = mode ? gW2[tid] : 0.f;
    }
    // stage whole W [k][n]
    for (int i = tid; i < 128 * 32; i += 256) {
        int k = i >> 5, n4 = i & 31;
        float4 v = ((const float4*)W)[i];
        float* dst = &sW[k * SW_STRIDE + n4 * 4];
        dst[0] = v.x; dst[1] = v.y; dst[2] = v.z; dst[3] = v.w;
    }

    int rowbase = blockIdx.x * 128;
    int warp = tid >> 5, lane = tid & 31;
    int g = lane >> 2, t = lane & 3;
    int wm = warp >> 1, wn = warp & 1;
    int mbase = wm * 32;
    int nbase = wn * 64;

    float acc[2][8][4];
    #pragma unroll
    for (int i = 0; i < 2; i++)
        #pragma unroll
        for (int j = 0; j < 8; j++)
            #pragma unroll
            for (int c = 0; c < 4; c++) acc[i][j][c] = 0.f;

    for (int k0 = 0; k0 < 128; k0 += 32) {
        __syncthreads();
        // stage A chunk with BN fused + tf32 hi/lo pre-split
        for (int i = tid; i < 128 * 8; i += 256) {
            int r = i >> 3, kq = i & 7;
            int gr = rowbase + r;
            float4 v = make_float4(0.f, 0.f, 0.f, 0.f);
            if (gr < M) v = *(const float4*)(A + (size_t)gr * HD + k0 + kq * 4);
            int c0 = k0 + kq * 4;
            float f0 = v.x * bna[c0 + 0] + bnc[c0 + 0];
            float f1 = v.y * bna[c0 + 1] + bnc[c0 + 1];
            float f2 = v.z * bna[c0 + 2] + bnc[c0 + 2];
            float f3 = v.w * bna[c0 + 3] + bnc[c0 + 3];
            int base = r * SA_STRIDE + kq * 4;
            split_tf32(f0, sAhi[base + 0], sAlo[base + 0]);
            split_tf32(f1, sAhi[base + 1], sAlo[base + 1]);
            split_tf32(f2, sAhi[base + 2], sAlo[base + 2]);
            split_tf32(f3, sAhi[base + 3], sAlo[base + 3]);
        }
        __syncthreads();
        #pragma unroll
        for (int ks = 0; ks < 32; ks += 8) {
            uint32_t ahi[2][4], alo[2][4];
            #pragma unroll
            for (int i = 0; i < 2; i++) {
                int r0 = (mbase + i * 16 + g) * SA_STRIDE;
                int r8 = r0 + 8 * SA_STRIDE;
                ahi[i][0] = sAhi[r0 + ks + t];     alo[i][0] = sAlo[r0 + ks + t];
                ahi[i][1] = sAhi[r8 + ks + t];     alo[i][1] = sAlo[r8 + ks + t];
                ahi[i][2] = sAhi[r0 + ks + t + 4]; alo[i][2] = sAlo[r0 + ks + t + 4];
                ahi[i][3] = sAhi[r8 + ks + t + 4]; alo[i][3] = sAlo[r8 + ks + t + 4];
            }
            #pragma unroll
            for (int j = 0; j < 8; j++) {
                int n = nbase + j * 8 + g;
                float f0 = sW[(k0 + ks + t) * SW_STRIDE + n];
                float f1 = sW[(k0 + ks + t + 4) * SW_STRIDE + n];
                uint32_t bh0, bl0, bh1, bl1;
                split_tf32(f0, bh0, bl0);
                split_tf32(f1, bh1, bl1);
                #pragma unroll
                for (int i = 0; i < 2; i++) {
                    mma_tf32(acc[i][j], ahi[i], bh0, bh1);
                    mma_tf32(acc[i][j], ahi[i], bl0, bl1);
                    mma_tf32(acc[i][j], alo[i], bh0, bh1);
                }
            }
        }
    }

    if (mode == 0) {
        #pragma unroll
        for (int i = 0; i < 2; i++) {
            int r  = rowbase + mbase + i * 16 + g;
            int r8 = r + 8;
            #pragma unroll
            for (int j = 0; j < 8; j++) {
                int col = nbase + j * 8 + 2 * t;
                if (r < M)
                    *(float2*)(g_t + (size_t)r * HD + col) = make_float2(acc[i][j][0], acc[i][j][1]);
                if (r8 < M)
                    *(float2*)(g_t + (size_t)r8 * HD + col) = make_float2(acc[i][j][2], acc[i][j][3]);
            }
        }
    } else {
        __syncthreads();           // reuse sAhi as rsum[128][2]
        float* rsum = (float*)sAhi;
        #pragma unroll
        for (int i = 0; i < 2; i++) {
            float s0 = 0.f, s1 = 0.f;
            #pragma unroll
            for (int j = 0; j < 8; j++) {
                int col = nbase + j * 8 + 2 * t;
                s0 += fmaxf(acc[i][j][0] + b1s[col], 0.f)     * w2s[col];
                s0 += fmaxf(acc[i][j][1] + b1s[col + 1], 0.f) * w2s[col + 1];
                s1 += fmaxf(acc[i][j][2] + b1s[col], 0.f)     * w2s[col];
                s1 += fmaxf(acc[i][j][3] + b1s[col + 1], 0.f) * w2s[col + 1];
            }
            s0 += __shfl_xor_sync(0xffffffffu, s0, 1);
            s0 += __shfl_xor_sync(0xffffffffu, s0, 2);
            s1 += __shfl_xor_sync(0xffffffffu, s1, 1);
            s1 += __shfl_xor_sync(0xffffffffu, s1, 2);
            if (t == 0) {
                int lr = mbase + i * 16 + g;
                rsum[lr * 2 + wn]       = s0;
                rsum[(lr + 8) * 2 + wn] = s1;
            }
        }
        __syncthreads();
        if (tid < 128) {
            int row = rowbase + tid;
            if (row < M) {
                float z = rsum[tid * 2] + rsum[tid * 2 + 1] + gb2[0];
                g_gate[row] = 1.f / (1.f + expf(-z));
            }
        }
    }
}

// ---------------- SpMM: g_h = relu(A_hat*g_t + bias); optional fused BN stats ----------------
__global__ void k_spmm(const float* __restrict__ bias, int N, int stats_en) {
    __shared__ __align__(16) float ssum[8 * 128];
    __shared__ __align__(16) float ssq[8 * 128];
    int warp = threadIdx.x >> 5, lane = threadIdx.x & 31;
    int v = blockIdx.x * 8 + warp;
    const int*   __restrict__ colp = (const int*)g_col;
    const float* __restrict__ wp   = (const float*)g_w;
    const float4* __restrict__ H4  = (const float4*)g_t;
    float4 acc = make_float4(0.f, 0.f, 0.f, 0.f);
    if (v < N) {
        int p = g_rowptr[v];
        int e = p + g_deg[v];
        for (; p + 3 < e; p += 4) {
            int s0 = colp[p], s1 = colp[p + 1], s2 = colp[p + 2], s3 = colp[p + 3];
            float w0 = wp[p], w1 = wp[p + 1], w2 = wp[p + 2], w3 = wp[p + 3];
            float4 h0 = H4[(size_t)s0 * 32 + lane];
            float4 h1 = H4[(size_t)s1 * 32 + lane];
            float4 h2 = H4[(size_t)s2 * 32 + lane];
            float4 h3 = H4[(size_t)s3 * 32 + lane];
            acc.x += w0 * h0.x + w1 * h1.x + w2 * h2.x + w3 * h3.x;
            acc.y += w0 * h0.y + w1 * h1.y + w2 * h2.y + w3 * h3.y;
            acc.z += w0 * h0.z + w1 * h1.z + w2 * h2.z + w3 * h3.z;
            acc.w += w0 * h0.w + w1 * h1.w + w2 * h2.w + w3 * h3.w;
        }
        for (; p < e; p++) {
            int s0 = colp[p]; float w0 = wp[p];
            float4 h0 = H4[(size_t)s0 * 32 + lane];
            acc.x += w0 * h0.x; acc.y += w0 * h0.y; acc.z += w0 * h0.z; acc.w += w0 * h0.w;
        }
        float di = g_dinv[v];
        float ws = di * di;
        float4 hs = H4[(size_t)v * 32 + lane];
        float4 b = ((const float4*)bias)[lane];
        acc.x = fmaxf(acc.x + ws * hs.x + b.x, 0.f);
        acc.y = fmaxf(acc.y + ws * hs.y + b.y, 0.f);
        acc.z = fmaxf(acc.z + ws * hs.z + b.z, 0.f);
        acc.w = fmaxf(acc.w + ws * hs.w + b.w, 0.f);
        ((float4*)g_h)[(size_t)v * 32 + lane] = acc;
    } else {
        acc = make_float4(0.f, 0.f, 0.f, 0.f);
    }
    if (stats_en) {
        int idx = warp * 128 + lane * 4;
        *(float4*)&ssum[idx] = acc;
        *(float4*)&ssq[idx] = make_float4(acc.x * acc.x, acc.y * acc.y, acc.z * acc.z, acc.w * acc.w);
        __syncthreads();
        int tid = threadIdx.x;
        if (tid < 128) {
            float s = 0.f, s2 = 0.f;
            #pragma unroll
            for (int w = 0; w < 8; w++) {
                s  += ssum[w * 128 + tid];
                s2 += ssq[w * 128 + tid];
            }
            atomicAdd(&g_stats[tid], s);
            atomicAdd(&g_stats[128 + tid], s2);
        }
    }
}

// ---------------- gated pooling ----------------
__device__ __forceinline__ int lower_bound_i32(const int* a, int n, int key) {
    int lo = 0, hi = n;
    while (lo < hi) { int mid = (lo + hi) >> 1; if (a[mid] < key) lo = mid + 1; else hi = mid; }
    return lo;
}

__global__ void k_pool(const int* __restrict__ batch, int N) {
    int g = blockIdx.x;
    int col = threadIdx.x;
    int start = lower_bound_i32(batch, N, g);
    int end   = lower_bound_i32(batch, N, g + 1);
    float s = 0.f;
    for (int r = start; r < end; r++)
        s += g_h[(size_t)r * HD + col] * g_gate[r];
    g_pool[g * HD + col] = s;
}

__global__ void k_bnpool(const float* __restrict__ gamma, const float* __restrict__ beta) {
    int c = threadIdx.x;
    float s = 0.f, s2 = 0.f;
    for (int r = 0; r < NGRAPH; r++) {
        float v = g_pool[r * HD + c];
        s += v; s2 += v * v;
    }
    float invG = 1.f / (float)NGRAPH;
    float mean = s * invG;
    float var  = s2 * invG - mean * mean;
    float a = gamma[c] * rsqrtf(var + 1e-5f);
    g_stats2[c] = a;
    g_stats2[128 + c] = beta[c] - mean * a;
}

__global__ void k_fc(const float* __restrict__ fcW, const float* __restrict__ fcb) {
    int g = blockIdx.x, t = threadIdx.x;
    __shared__ float srow[128];
    srow[t] = g_pool[g * HD + t] * g_stats2[t] + g_stats2[128 + t];
    __syncthreads();
    float acc = fcb[t];
    #pragma unroll
    for (int k = 0; k < 128; k++)
        acc += srow[k] * fcW[k * 128 + t];
    g_g2[g * HD + t] = fmaxf(acc, 0.f);
}

__global__ void k_cls(const float* __restrict__ clsW, const float* __restrict__ clsb,
                      float* __restrict__ out) {
    int g = blockIdx.x, t = threadIdx.x;
    __shared__ float srow[128];
    __shared__ float lg[10];
    __shared__ float s_lse;
    for (int i = t; i < 128; i += 32) srow[i] = g_g2[g * HD + i];
    __syncthreads();
    if (t < 10) {
        float a = clsb[t];
        #pragma unroll
        for (int k = 0; k < 128; k++) a += srow[k] * clsW[k * 10 + t];
        lg[t] = a;
    }
    __syncthreads();
    if (t == 0) {
        float m = lg[0];
        #pragma unroll
        for (int i = 1; i < 10; i++) m = fmaxf(m, lg[i]);
        float s = 0.f;
        #pragma unroll
        for (int i = 0; i < 10; i++) s += expf(lg[i] - m);
        s_lse = m + logf(s);
    }
    __syncthreads();
    if (t < 10) out[g * 10 + t] = lg[t] - s_lse;
}

// ---------------- launch ----------------
extern "C" void kernel_launch(void* const* d_in, const int* in_sizes, int n_in,
                              void* d_out, int out_size) {
    const float* x           = (const float*)d_in[0];
    const int*   eidx        = (const int*)d_in[1];    // int32 (JAX x64 disabled)
    const int*   batch       = (const int*)d_in[2];
    const float* bn_feat_g   = (const float*)d_in[3];
    const float* bn_feat_b   = (const float*)d_in[4];
    const float* conv_feat_W = (const float*)d_in[5];
    const float* conv_feat_b = (const float*)d_in[6];
    const float* conv_W      = (const float*)d_in[7];
    const float* conv_b      = (const float*)d_in[8];
    const float* bn_conv_g   = (const float*)d_in[9];
    const float* bn_conv_b   = (const float*)d_in[10];
    const float* gate_W1     = (const float*)d_in[11];
    const float* gate_b1     = (const float*)d_in[12];
    const float* gate_W2     = (const float*)d_in[13];
    const float* gate_b2     = (const float*)d_in[14];
    const float* fc_W        = (const float*)d_in[15];
    const float* fc_b        = (const float*)d_in[16];
    const float* bn_fc_g     = (const float*)d_in[17];
    const float* bn_fc_b     = (const float*)d_in[18];
    const float* cls_W       = (const float*)d_in[19];
    const float* cls_b       = (const float*)d_in[20];
    float* out = (float*)d_out;

    int N = in_sizes[0] / HD;
    int E = in_sizes[1] / 2;
    int NB = (N + 1023) >> 10;
    int EB = (E + 255) / 256;
    int GB = (N + 127) / 128;
    int SB = (N + 7) / 8;
    float invN = 1.f / (float)N;

    static int smem_set = 0;
    int smem_bytes = SMEM_FLOATS * 4;
    if (!smem_set) {
        cudaFuncSetAttribute(k_gemm_tc, cudaFuncAttributeMaxDynamicSharedMemorySize, smem_bytes);
        smem_set = 1;
    }

    // graph structure (CSR by counting sort)
    k_zero_deg<<<(N + 255) / 256, 256>>>(N);
    k_deg<<<EB, 256>>>(eidx, E);
    k_scan1<<<NB, 256>>>(N);
    k_scan2<<<1, 64>>>(NB);
    k_scan3<<<NB, 1024>>>(N);
    k_scatter<<<EB, 256>>>(eidx, E);

    // layer 0: stats of x -> BN -> GEMM -> SpMM (+stats of h for next BN)
    k_colstats<<<1184, 128>>>(x, N);
    k_bnfinal<<<1, 128>>>(bn_feat_g, bn_feat_b, invN);
    k_gemm_tc<<<GB, 256, smem_bytes>>>(x, 0, conv_feat_W, 1, 0, N, nullptr, nullptr, nullptr);
    k_spmm<<<SB, 256>>>(conv_feat_b, N, 1);

    // conv layers 1..3 (stats come fused from the previous SpMM)
    for (int i = 0; i < 3; i++) {
        k_bnfinal<<<1, 128>>>(bn_conv_g + i * 128, bn_conv_b + i * 128, invN);
        k_gemm_tc<<<GB, 256, smem_bytes>>>(nullptr, 1, conv_W + i * 128 * 128, 1, 0, N, nullptr, nullptr, nullptr);
        k_spmm<<<SB, 256>>>(conv_b + i * 128, N, i < 2 ? 1 : 0);  // last: keep stats zeroed
    }

    // gate (fused GEMM + relu + dot W2 + sigmoid)
    k_gemm_tc<<<GB, 256, smem_bytes>>>(nullptr, 1, gate_W1, 0, 1, N, gate_b1, gate_W2, gate_b2);

    // pooling + head
    k_pool<<<NGRAPH, 128>>>(batch, N);
    k_bnpool<<<1, 128>>>(bn_fc_g, bn_fc_b);
    k_fc<<<NGRAPH, 128>>>(fc_W, fc_b);
    k_cls<<<NGRAPH, 32>>>(cls_W, cls_b, out);
}

// round 10
// speedup vs baseline: 1.6012x; 1.1934x over previous
#include <cuda_runtime.h>
#include <cuda_bf16.h>
#include <math.h>
#include <stdint.h>

#define NMAX 50000
#define EMAX 600000
#define NGRAPH 256
#define HD 128

// ---------------- device scratch ----------------
__device__ __align__(16) int   g_deg[NMAX];
__device__ __align__(16) float g_dinv[NMAX];
__device__ __align__(16) int   g_rowptr[NMAX];
__device__ __align__(16) int   g_cursor[NMAX];
__device__ __align__(16) int   g_col[EMAX];
__device__ __align__(16) float g_w[EMAX];
__device__ __align__(16) float g_h[NMAX * HD];
__device__ __align__(16) float g_t[NMAX * HD];
__device__ __align__(16) float g_gate[NMAX];
__device__ __align__(16) float g_stats[512];   // sum | sumsq | a | c
__device__ __align__(16) float g_stats2[256];
__device__ __align__(16) float g_pool[NGRAPH * HD];
__device__ __align__(16) float g_g2[NGRAPH * HD];
__device__ __align__(16) int   g_part[128];

// ---------------- graph structure build ----------------
__global__ void k_zero_deg(int N) {
    int i = blockIdx.x * blockDim.x + threadIdx.x;
    if (i < N) g_deg[i] = 0;
}

__global__ void k_deg(const int* __restrict__ eidx, int E) {
    int e = blockIdx.x * blockDim.x + threadIdx.x;
    if (e < E) atomicAdd(&g_deg[eidx[E + e]], 1);
}

__global__ void k_scan1(int N) {
    __shared__ int sh[256];
    int t = threadIdx.x;
    int base = blockIdx.x * 1024;
    int s = 0;
    #pragma unroll
    for (int j = 0; j < 4; j++) {
        int i = base + t + j * 256;
        if (i < N) s += g_deg[i];
    }
    sh[t] = s; __syncthreads();
    for (int off = 128; off > 0; off >>= 1) {
        if (t < off) sh[t] += sh[t + off];
        __syncthreads();
    }
    if (t == 0) g_part[blockIdx.x] = sh[0];
}

__global__ void k_scan2(int NB) {   // <<<1,64>>>
    __shared__ int sh[64];
    int t = threadIdx.x;
    int v = (t < NB) ? g_part[t] : 0;
    sh[t] = v; __syncthreads();
    for (int off = 1; off < 64; off <<= 1) {
        int x = (t >= off) ? sh[t - off] : 0;
        __syncthreads();
        sh[t] += x;
        __syncthreads();
    }
    if (t < NB) g_part[t] = sh[t] - v;
}

__global__ void k_scan3(int N) {
    __shared__ int sh[1024];
    int t = threadIdx.x;
    int i = blockIdx.x * 1024 + t;
    int v = (i < N) ? g_deg[i] : 0;
    sh[t] = v; __syncthreads();
    for (int off = 1; off < 1024; off <<= 1) {
        int x = (t >= off) ? sh[t - off] : 0;
        __syncthreads();
        sh[t] += x;
        __syncthreads();
    }
    if (i < N) {
        int excl = sh[t] - v;
        int start = g_part[blockIdx.x] + excl;
        g_rowptr[i] = start;
        g_cursor[i] = start;
        g_dinv[i] = rsqrtf((float)v + 1.0f);
    }
}

__global__ void k_scatter(const int* __restrict__ eidx, int E) {
    int e = blockIdx.x * blockDim.x + threadIdx.x;
    if (e < E) {
        int src = eidx[e];
        int dst = eidx[E + e];
        int pos = atomicAdd(&g_cursor[dst], 1);
        g_col[pos] = src;
        g_w[pos] = g_dinv[src] * g_dinv[dst];
    }
}

// ---------------- BatchNorm statistics ----------------
__global__ void k_colstats(const float* __restrict__ X, int N) {
    int col = threadIdx.x;  // 128
    float s = 0.f, s2 = 0.f;
    for (int r = blockIdx.x; r < N; r += gridDim.x) {
        float v = X[(size_t)r * HD + col];
        s += v; s2 += v * v;
    }
    atomicAdd(&g_stats[col], s);
    atomicAdd(&g_stats[128 + col], s2);
}

// consumes sum/sumsq, produces a/c, re-zeroes sum/sumsq (replay-deterministic)
__global__ void k_bnfinal(const float* __restrict__ gamma, const float* __restrict__ beta, float invN) {
    int c = threadIdx.x;
    float mean = g_stats[c] * invN;
    float var  = g_stats[128 + c] * invN - mean * mean;
    float a = gamma[c] * rsqrtf(var + 1e-5f);
    g_stats[256 + c] = a;
    g_stats[384 + c] = beta[c] - mean * a;
    g_stats[c] = 0.f;
    g_stats[128 + c] = 0.f;
}

// ---------------- tensor-core GEMM (3xBF16 split, m16n8k16) ----------------
__device__ __forceinline__ void mma_bf16(float* c, const uint32_t* a, uint32_t b0, uint32_t b1) {
    asm volatile(
        "mma.sync.aligned.m16n8k16.row.col.f32.bf16.bf16.f32 "
        "{%0,%1,%2,%3}, {%4,%5,%6,%7}, {%8,%9}, {%0,%1,%2,%3};"
        : "+f"(c[0]), "+f"(c[1]), "+f"(c[2]), "+f"(c[3])
        : "r"(a[0]), "r"(a[1]), "r"(a[2]), "r"(a[3]), "r"(b0), "r"(b1));
}
// split x into bf16 hi + bf16 lo (hi rn, lo rn of residual)
__device__ __forceinline__ void split_bf16(float x, __nv_bfloat16& hi, __nv_bfloat16& lo) {
    hi = __float2bfloat16_rn(x);
    lo = __float2bfloat16_rn(x - __bfloat162float(hi));
}
__device__ __forceinline__ uint32_t pack2(__nv_bfloat16 e0, __nv_bfloat16 e1) {
    __nv_bfloat162 p(e0, e1);   // e0 -> low half (even k), e1 -> high half (odd k)
    return *(uint32_t*)&p;
}

#define SWS 136   // word stride of packed W: banks (8t+8j+g) -> conflict-free
#define AST 36    // word stride of packed A: banks (4g+t)    -> conflict-free
// words: sWhi[64*136] sWlo[64*136] | sAhi[128*36] sAlo[128*36] | params 512 floats
#define SMEM_WORDS (2 * 64 * SWS + 2 * 128 * AST + 512)

__global__ __launch_bounds__(256, 2) void k_gemm_tc(
    const float* __restrict__ Aext, int sel, const float* __restrict__ W,
    int use_bn, int mode, int M,
    const float* __restrict__ gb1, const float* __restrict__ gW2,
    const float* __restrict__ gb2)
{
    extern __shared__ uint32_t smw[];
    uint32_t* sWhi = smw;
    uint32_t* sWlo = sWhi + 64 * SWS;
    uint32_t* sAhi = sWlo + 64 * SWS;
    uint32_t* sAlo = sAhi + 128 * AST;
    float*    bna  = (float*)(sAlo + 128 * AST);
    float*    bnc  = bna + 128;
    float*    b1s  = bnc + 128;
    float*    w2s  = b1s + 128;

    const float* __restrict__ A = sel ? (const float*)g_h : Aext;
    int tid = threadIdx.x;

    if (tid < 128) {
        bna[tid] = use_bn ? g_stats[256 + tid] : 1.f;
        bnc[tid] = use_bn ? g_stats[384 + tid] : 0.f;
        b1s[tid] = mode ? gb1[tid] : 0.f;
        w2s[tid] = mode ? gW2[tid] : 0.f;
    }
    // stage + split whole W: packed [kp][n] with word = (k=2kp, k=2kp+1) per column n
    for (int i = tid; i < 64 * 32; i += 256) {
        int kp = i >> 5, n4 = i & 31;
        float4 w0 = ((const float4*)(W + (2 * kp) * 128))[n4];
        float4 w1 = ((const float4*)(W + (2 * kp + 1) * 128))[n4];
        float e0[4] = {w0.x, w0.y, w0.z, w0.w};
        float e1[4] = {w1.x, w1.y, w1.z, w1.w};
        #pragma unroll
        for (int c = 0; c < 4; c++) {
            __nv_bfloat16 h0, l0, h1, l1;
            split_bf16(e0[c], h0, l0);
            split_bf16(e1[c], h1, l1);
            sWhi[kp * SWS + n4 * 4 + c] = pack2(h0, h1);
            sWlo[kp * SWS + n4 * 4 + c] = pack2(l0, l1);
        }
    }

    int rowbase = blockIdx.x * 128;
    int warp = tid >> 5, lane = tid & 31;
    int g = lane >> 2, t = lane & 3;
    int wm = warp >> 1, wn = warp & 1;
    int mbase = wm * 32;
    int nbase = wn * 64;

    float acc[2][8][4];
    #pragma unroll
    for (int i = 0; i < 2; i++)
        #pragma unroll
        for (int j = 0; j < 8; j++)
            #pragma unroll
            for (int c = 0; c < 4; c++) acc[i][j][c] = 0.f;

    for (int k0 = 0; k0 < 128; k0 += 32) {
        __syncthreads();
        // stage A chunk: BN fused, bf16 hi/lo split, packed pairs [row][kp 0..15]
        for (int i = tid; i < 128 * 8; i += 256) {
            int r = i >> 3, kq = i & 7;            // kq: float4 index within 32-k chunk
            int gr = rowbase + r;
            float4 v = make_float4(0.f, 0.f, 0.f, 0.f);
            if (gr < M) v = *(const float4*)(A + (size_t)gr * HD + k0 + kq * 4);
            int c0 = k0 + kq * 4;
            float f0 = v.x * bna[c0 + 0] + bnc[c0 + 0];
            float f1 = v.y * bna[c0 + 1] + bnc[c0 + 1];
            float f2 = v.z * bna[c0 + 2] + bnc[c0 + 2];
            float f3 = v.w * bna[c0 + 3] + bnc[c0 + 3];
            __nv_bfloat16 h0, l0, h1, l1, h2, l2, h3, l3;
            split_bf16(f0, h0, l0);
            split_bf16(f1, h1, l1);
            split_bf16(f2, h2, l2);
            split_bf16(f3, h3, l3);
            int base = r * AST + kq * 2;
            sAhi[base]     = pack2(h0, h1);
            sAhi[base + 1] = pack2(h2, h3);
            sAlo[base]     = pack2(l0, l1);
            sAlo[base + 1] = pack2(l2, l3);
        }
        __syncthreads();
        #pragma unroll
        for (int ks2 = 0; ks2 < 2; ks2++) {        // two k16 sub-tiles per 32-chunk
            int kpl = ks2 * 8;                     // local kp base in sA
            int kpg = (k0 >> 1) + kpl;             // global kp base in sW
            uint32_t ahi[2][4], alo[2][4];
            #pragma unroll
            for (int i = 0; i < 2; i++) {
                int r0 = (mbase + i * 16 + g) * AST;
                int r8 = r0 + 8 * AST;
                ahi[i][0] = sAhi[r0 + kpl + t];     alo[i][0] = sAlo[r0 + kpl + t];
                ahi[i][1] = sAhi[r8 + kpl + t];     alo[i][1] = sAlo[r8 + kpl + t];
                ahi[i][2] = sAhi[r0 + kpl + t + 4]; alo[i][2] = sAlo[r0 + kpl + t + 4];
                ahi[i][3] = sAhi[r8 + kpl + t + 4]; alo[i][3] = sAlo[r8 + kpl + t + 4];
            }
            #pragma unroll
            for (int j = 0; j < 8; j++) {
                int n = nbase + j * 8 + g;
                uint32_t bh0 = sWhi[(kpg + t) * SWS + n];
                uint32_t bh1 = sWhi[(kpg + t + 4) * SWS + n];
                uint32_t bl0 = sWlo[(kpg + t) * SWS + n];
                uint32_t bl1 = sWlo[(kpg + t + 4) * SWS + n];
                #pragma unroll
                for (int i = 0; i < 2; i++) {
                    mma_bf16(acc[i][j], ahi[i], bh0, bh1);   // hi*hi
                    mma_bf16(acc[i][j], ahi[i], bl0, bl1);   // hi*lo
                    mma_bf16(acc[i][j], alo[i], bh0, bh1);   // lo*hi
                }
            }
        }
    }

    if (mode == 0) {
        #pragma unroll
        for (int i = 0; i < 2; i++) {
            int r  = rowbase + mbase + i * 16 + g;
            int r8 = r + 8;
            #pragma unroll
            for (int j = 0; j < 8; j++) {
                int col = nbase + j * 8 + 2 * t;
                if (r < M)
                    *(float2*)(g_t + (size_t)r * HD + col) = make_float2(acc[i][j][0], acc[i][j][1]);
                if (r8 < M)
                    *(float2*)(g_t + (size_t)r8 * HD + col) = make_float2(acc[i][j][2], acc[i][j][3]);
            }
        }
    } else {
        __syncthreads();           // reuse sAhi as rsum[128][2]
        float* rsum = (float*)sAhi;
        #pragma unroll
        for (int i = 0; i < 2; i++) {
            float s0 = 0.f, s1 = 0.f;
            #pragma unroll
            for (int j = 0; j < 8; j++) {
                int col = nbase + j * 8 + 2 * t;
                s0 += fmaxf(acc[i][j][0] + b1s[col], 0.f)     * w2s[col];
                s0 += fmaxf(acc[i][j][1] + b1s[col + 1], 0.f) * w2s[col + 1];
                s1 += fmaxf(acc[i][j][2] + b1s[col], 0.f)     * w2s[col];
                s1 += fmaxf(acc[i][j][3] + b1s[col + 1], 0.f) * w2s[col + 1];
            }
            s0 += __shfl_xor_sync(0xffffffffu, s0, 1);
            s0 += __shfl_xor_sync(0xffffffffu, s0, 2);
            s1 += __shfl_xor_sync(0xffffffffu, s1, 1);
            s1 += __shfl_xor_sync(0xffffffffu, s1, 2);
            if (t == 0) {
                int lr = mbase + i * 16 + g;
                rsum[lr * 2 + wn]       = s0;
                rsum[(lr + 8) * 2 + wn] = s1;
            }
        }
        __syncthreads();
        if (tid < 128) {
            int row = rowbase + tid;
            if (row < M) {
                float z = rsum[tid * 2] + rsum[tid * 2 + 1] + gb2[0];
                g_gate[row] = 1.f / (1.f + expf(-z));
            }
        }
    }
}

// ---------------- SpMM: g_h = relu(A_hat*g_t + bias); optional fused BN stats ----------------
__global__ void k_spmm(const float* __restrict__ bias, int N, int stats_en) {
    __shared__ __align__(16) float ssum[8 * 128];
    __shared__ __align__(16) float ssq[8 * 128];
    int warp = threadIdx.x >> 5, lane = threadIdx.x & 31;
    int v = blockIdx.x * 8 + warp;
    const int*   __restrict__ colp = (const int*)g_col;
    const float* __restrict__ wp   = (const float*)g_w;
    const float4* __restrict__ H4  = (const float4*)g_t;
    float4 acc = make_float4(0.f, 0.f, 0.f, 0.f);
    if (v < N) {
        int p = g_rowptr[v];
        int e = p + g_deg[v];
        for (; p + 3 < e; p += 4) {
            int s0 = colp[p], s1 = colp[p + 1], s2 = colp[p + 2], s3 = colp[p + 3];
            float w0 = wp[p], w1 = wp[p + 1], w2 = wp[p + 2], w3 = wp[p + 3];
            float4 h0 = H4[(size_t)s0 * 32 + lane];
            float4 h1 = H4[(size_t)s1 * 32 + lane];
            float4 h2 = H4[(size_t)s2 * 32 + lane];
            float4 h3 = H4[(size_t)s3 * 32 + lane];
            acc.x += w0 * h0.x + w1 * h1.x + w2 * h2.x + w3 * h3.x;
            acc.y += w0 * h0.y + w1 * h1.y + w2 * h2.y + w3 * h3.y;
            acc.z += w0 * h0.z + w1 * h1.z + w2 * h2.z + w3 * h3.z;
            acc.w += w0 * h0.w + w1 * h1.w + w2 * h2.w + w3 * h3.w;
        }
        for (; p < e; p++) {
            int s0 = colp[p]; float w0 = wp[p];
            float4 h0 = H4[(size_t)s0 * 32 + lane];
            acc.x += w0 * h0.x; acc.y += w0 * h0.y; acc.z += w0 * h0.z; acc.w += w0 * h0.w;
        }
        float di = g_dinv[v];
        float ws = di * di;
        float4 hs = H4[(size_t)v * 32 + lane];
        float4 b = ((const float4*)bias)[lane];
        acc.x = fmaxf(acc.x + ws * hs.x + b.x, 0.f);
        acc.y = fmaxf(acc.y + ws * hs.y + b.y, 0.f);
        acc.z = fmaxf(acc.z + ws * hs.z + b.z, 0.f);
        acc.w = fmaxf(acc.w + ws * hs.w + b.w, 0.f);
        ((float4*)g_h)[(size_t)v * 32 + lane] = acc;
    } else {
        acc = make_float4(0.f, 0.f, 0.f, 0.f);
    }
    if (stats_en) {
        int idx = warp * 128 + lane * 4;
        *(float4*)&ssum[idx] = acc;
        *(float4*)&ssq[idx] = make_float4(acc.x * acc.x, acc.y * acc.y, acc.z * acc.z, acc.w * acc.w);
        __syncthreads();
        int tid = threadIdx.x;
        if (tid < 128) {
            float s = 0.f, s2 = 0.f;
            #pragma unroll
            for (int w = 0; w < 8; w++) {
                s  += ssum[w * 128 + tid];
                s2 += ssq[w * 128 + tid];
            }
            atomicAdd(&g_stats[tid], s);
            atomicAdd(&g_stats[128 + tid], s2);
        }
    }
}

// ---------------- gated pooling ----------------
__device__ __forceinline__ int lower_bound_i32(const int* a, int n, int key) {
    int lo = 0, hi = n;
    while (lo < hi) { int mid = (lo + hi) >> 1; if (a[mid] < key) lo = mid + 1; else hi = mid; }
    return lo;
}

__global__ void k_pool(const int* __restrict__ batch, int N) {
    int g = blockIdx.x;
    int col = threadIdx.x;
    int start = lower_bound_i32(batch, N, g);
    int end   = lower_bound_i32(batch, N, g + 1);
    float s = 0.f;
    for (int r = start; r < end; r++)
        s += g_h[(size_t)r * HD + col] * g_gate[r];
    g_pool[g * HD + col] = s;
}

__global__ void k_bnpool(const float* __restrict__ gamma, const float* __restrict__ beta) {
    int c = threadIdx.x;
    float s = 0.f, s2 = 0.f;
    for (int r = 0; r < NGRAPH; r++) {
        float v = g_pool[r * HD + c];
        s += v; s2 += v * v;
    }
    float invG = 1.f / (float)NGRAPH;
    float mean = s * invG;
    float var  = s2 * invG - mean * mean;
    float a = gamma[c] * rsqrtf(var + 1e-5f);
    g_stats2[c] = a;
    g_stats2[128 + c] = beta[c] - mean * a;
}

__global__ void k_fc(const float* __restrict__ fcW, const float* __restrict__ fcb) {
    int g = blockIdx.x, t = threadIdx.x;
    __shared__ float srow[128];
    srow[t] = g_pool[g * HD + t] * g_stats2[t] + g_stats2[128 + t];
    __syncthreads();
    float acc = fcb[t];
    #pragma unroll
    for (int k = 0; k < 128; k++)
        acc += srow[k] * fcW[k * 128 + t];
    g_g2[g * HD + t] = fmaxf(acc, 0.f);
}

__global__ void k_cls(const float* __restrict__ clsW, const float* __restrict__ clsb,
                      float* __restrict__ out) {
    int g = blockIdx.x, t = threadIdx.x;
    __shared__ float srow[128];
    __shared__ float lg[10];
    __shared__ float s_lse;
    for (int i = t; i < 128; i += 32) srow[i] = g_g2[g * HD + i];
    __syncthreads();
    if (t < 10) {
        float a = clsb[t];
        #pragma unroll
        for (int k = 0; k < 128; k++) a += srow[k] * clsW[k * 10 + t];
        lg[t] = a;
    }
    __syncthreads();
    if (t == 0) {
        float m = lg[0];
        #pragma unroll
        for (int i = 1; i < 10; i++) m = fmaxf(m, lg[i]);
        float s = 0.f;
        #pragma unroll
        for (int i = 0; i < 10; i++) s += expf(lg[i] - m);
        s_lse = m + logf(s);
    }
    __syncthreads();
    if (t < 10) out[g * 10 + t] = lg[t] - s_lse;
}

// ---------------- launch ----------------
extern "C" void kernel_launch(void* const* d_in, const int* in_sizes, int n_in,
                              void* d_out, int out_size) {
    const float* x           = (const float*)d_in[0];
    const int*   eidx        = (const int*)d_in[1];    // int32 (JAX x64 disabled)
    const int*   batch       = (const int*)d_in[2];
    const float* bn_feat_g   = (const float*)d_in[3];
    const float* bn_feat_b   = (const float*)d_in[4];
    const float* conv_feat_W = (const float*)d_in[5];
    const float* conv_feat_b = (const float*)d_in[6];
    const float* conv_W      = (const float*)d_in[7];
    const float* conv_b      = (const float*)d_in[8];
    const float* bn_conv_g   = (const float*)d_in[9];
    const float* bn_conv_b   = (const float*)d_in[10];
    const float* gate_W1     = (const float*)d_in[11];
    const float* gate_b1     = (const float*)d_in[12];
    const float* gate_W2     = (const float*)d_in[13];
    const float* gate_b2     = (const float*)d_in[14];
    const float* fc_W        = (const float*)d_in[15];
    const float* fc_b        = (const float*)d_in[16];
    const float* bn_fc_g     = (const float*)d_in[17];
    const float* bn_fc_b     = (const float*)d_in[18];
    const float* cls_W       = (const float*)d_in[19];
    const float* cls_b       = (const float*)d_in[20];
    float* out = (float*)d_out;

    int N = in_sizes[0] / HD;
    int E = in_sizes[1] / 2;
    int NB = (N + 1023) >> 10;
    int EB = (E + 255) / 256;
    int GB = (N + 127) / 128;
    int SB = (N + 7) / 8;
    float invN = 1.f / (float)N;

    static int smem_set = 0;
    int smem_bytes = SMEM_WORDS * 4;
    if (!smem_set) {
        cudaFuncSetAttribute(k_gemm_tc, cudaFuncAttributeMaxDynamicSharedMemorySize, smem_bytes);
        smem_set = 1;
    }

    // graph structure (CSR by counting sort)
    k_zero_deg<<<(N + 255) / 256, 256>>>(N);
    k_deg<<<EB, 256>>>(eidx, E);
    k_scan1<<<NB, 256>>>(N);
    k_scan2<<<1, 64>>>(NB);
    k_scan3<<<NB, 1024>>>(N);
    k_scatter<<<EB, 256>>>(eidx, E);

    // layer 0
    k_colstats<<<1184, 128>>>(x, N);
    k_bnfinal<<<1, 128>>>(bn_feat_g, bn_feat_b, invN);
    k_gemm_tc<<<GB, 256, smem_bytes>>>(x, 0, conv_feat_W, 1, 0, N, nullptr, nullptr, nullptr);
    k_spmm<<<SB, 256>>>(conv_feat_b, N, 1);

    // conv layers 1..3 (stats fused from previous SpMM)
    for (int i = 0; i < 3; i++) {
        k_bnfinal<<<1, 128>>>(bn_conv_g + i * 128, bn_conv_b + i * 128, invN);
        k_gemm_tc<<<GB, 256, smem_bytes>>>(nullptr, 1, conv_W + i * 128 * 128, 1, 0, N, nullptr, nullptr, nullptr);
        k_spmm<<<SB, 256>>>(conv_b + i * 128, N, i < 2 ? 1 : 0);
    }

    // gate (fused GEMM + relu + dot W2 + sigmoid)
    k_gemm_tc<<<GB, 256, smem_bytes>>>(nullptr, 1, gate_W1, 0, 1, N, gate_b1, gate_W2, gate_b2);

    // pooling + head
    k_pool<<<NGRAPH, 128>>>(batch, N);
    k_bnpool<<<1, 128>>>(bn_fc_g, bn_fc_b);
    k_fc<<<NGRAPH, 128>>>(fc_W, fc_b);
    k_cls<<<NGRAPH, 32>>>(cls_W, cls_b, out);
}

// round 11
// speedup vs baseline: 1.7260x; 1.0779x over previous
#include <cuda_runtime.h>
#include <cuda_bf16.h>
#include <math.h>
#include <stdint.h>

#define NMAX 50000
#define EMAX 600000
#define NGRAPH 256
#define HD 128

// ---------------- device scratch ----------------
__device__ __align__(16) int   g_deg[NMAX];
__device__ __align__(16) float g_dinv[NMAX];
__device__ __align__(16) int   g_rowptr[NMAX];
__device__ __align__(16) int   g_cursor[NMAX];
__device__ __align__(16) int   g_col[EMAX];
__device__ __align__(16) float g_w[EMAX];
__device__ __align__(16) float g_h[NMAX * HD];
__device__ __align__(16) float g_t[NMAX * HD];
__device__ __align__(16) float g_gate[NMAX];
// two ping-pong stat slots: slot s -> sum at [s*256, s*256+128), sumsq at [s*256+128, s*256+256)
__device__ __align__(16) float g_stats[512];
__device__ __align__(16) float g_stats2[256];
__device__ __align__(16) float g_pool[NGRAPH * HD];
__device__ __align__(16) float g_g2[NGRAPH * HD];
__device__ __align__(16) int   g_part[128];

// ---------------- graph structure build ----------------
__global__ void k_zero_deg(int N) {
    int i = blockIdx.x * blockDim.x + threadIdx.x;
    if (i < N) g_deg[i] = 0;
}

__global__ void k_deg(const int* __restrict__ eidx, int E) {
    int e = blockIdx.x * blockDim.x + threadIdx.x;
    if (e < E) atomicAdd(&g_deg[eidx[E + e]], 1);
}

__global__ void k_scan1(int N) {
    __shared__ int sh[256];
    int t = threadIdx.x;
    int base = blockIdx.x * 1024;
    int s = 0;
    #pragma unroll
    for (int j = 0; j < 4; j++) {
        int i = base + t + j * 256;
        if (i < N) s += g_deg[i];
    }
    sh[t] = s; __syncthreads();
    for (int off = 128; off > 0; off >>= 1) {
        if (t < off) sh[t] += sh[t + off];
        __syncthreads();
    }
    if (t == 0) g_part[blockIdx.x] = sh[0];
}

__global__ void k_scan2(int NB) {   // <<<1,64>>>
    __shared__ int sh[64];
    int t = threadIdx.x;
    int v = (t < NB) ? g_part[t] : 0;
    sh[t] = v; __syncthreads();
    for (int off = 1; off < 64; off <<= 1) {
        int x = (t >= off) ? sh[t - off] : 0;
        __syncthreads();
        sh[t] += x;
        __syncthreads();
    }
    if (t < NB) g_part[t] = sh[t] - v;
}

__global__ void k_scan3(int N) {
    __shared__ int sh[1024];
    int t = threadIdx.x;
    int i = blockIdx.x * 1024 + t;
    int v = (i < N) ? g_deg[i] : 0;
    sh[t] = v; __syncthreads();
    for (int off = 1; off < 1024; off <<= 1) {
        int x = (t >= off) ? sh[t - off] : 0;
        __syncthreads();
        sh[t] += x;
        __syncthreads();
    }
    if (i < N) {
        int excl = sh[t] - v;
        int start = g_part[blockIdx.x] + excl;
        g_rowptr[i] = start;
        g_cursor[i] = start;
        g_dinv[i] = rsqrtf((float)v + 1.0f);
    }
}

__global__ void k_scatter(const int* __restrict__ eidx, int E) {
    int e = blockIdx.x * blockDim.x + threadIdx.x;
    if (e < E) {
        int src = eidx[e];
        int dst = eidx[E + e];
        int pos = atomicAdd(&g_cursor[dst], 1);
        g_col[pos] = src;
        g_w[pos] = g_dinv[src] * g_dinv[dst];
    }
}

// ---------------- BN statistics for external input x (slot 0) ----------------
__global__ void k_colstats(const float* __restrict__ X, int N) {
    int col = threadIdx.x;  // 128
    float s = 0.f, s2 = 0.f;
    for (int r = blockIdx.x; r < N; r += gridDim.x) {
        float v = X[(size_t)r * HD + col];
        s += v; s2 += v * v;
    }
    atomicAdd(&g_stats[col], s);
    atomicAdd(&g_stats[128 + col], s2);
}

// ---------------- tensor-core GEMM (3xBF16 split, m16n8k16, reg-prefetch pipeline) ----------------
__device__ __forceinline__ void mma_bf16(float* c, const uint32_t* a, uint32_t b0, uint32_t b1) {
    asm volatile(
        "mma.sync.aligned.m16n8k16.row.col.f32.bf16.bf16.f32 "
        "{%0,%1,%2,%3}, {%4,%5,%6,%7}, {%8,%9}, {%0,%1,%2,%3};"
        : "+f"(c[0]), "+f"(c[1]), "+f"(c[2]), "+f"(c[3])
        : "r"(a[0]), "r"(a[1]), "r"(a[2]), "r"(a[3]), "r"(b0), "r"(b1));
}
__device__ __forceinline__ void split_bf16(float x, __nv_bfloat16& hi, __nv_bfloat16& lo) {
    hi = __float2bfloat16_rn(x);
    lo = __float2bfloat16_rn(x - __bfloat162float(hi));
}
__device__ __forceinline__ uint32_t pack2(__nv_bfloat16 e0, __nv_bfloat16 e1) {
    __nv_bfloat162 p(e0, e1);
    return *(uint32_t*)&p;
}

#define SWS 136   // packed W word stride: (8t+g) bank map -> conflict-free
#define AST 20    // packed A word stride: (20g+t) bank map -> conflict-free
// words: sWhi[64*136] sWlo[64*136] | sAhi[128*20] sAlo[128*20] | params 512
#define SMEM_WORDS (2 * 64 * SWS + 2 * 128 * AST + 512)

// slot: BN stats slot to read (-1 = no BN). zslot: stats slot to zero (-1 = none).
// mode 0: write g_t. mode 1: gate epilogue -> g_gate.
__global__ __launch_bounds__(256, 2) void k_gemm_tc(
    const float* __restrict__ Aext, int sel, const float* __restrict__ W,
    int slot, int zslot, float invN,
    const float* __restrict__ gamma, const float* __restrict__ beta,
    int mode, int M,
    const float* __restrict__ gb1, const float* __restrict__ gW2,
    const float* __restrict__ gb2)
{
    extern __shared__ uint32_t smw[];
    uint32_t* sWhi = smw;
    uint32_t* sWlo = sWhi + 64 * SWS;
    uint32_t* sAhi = sWlo + 64 * SWS;
    uint32_t* sAlo = sAhi + 128 * AST;
    float*    bna  = (float*)(sAlo + 128 * AST);
    float*    bnc  = bna + 128;
    float*    b1s  = bnc + 128;
    float*    w2s  = b1s + 128;

    const float* __restrict__ A = sel ? (const float*)g_h : Aext;
    int tid = threadIdx.x;

    // fused BN finalize: every block computes a/c from raw sums (cheap, redundant)
    if (tid < 128) {
        float a = 1.f, cc = 0.f;
        if (slot >= 0) {
            float mean = g_stats[slot * 256 + tid] * invN;
            float var  = g_stats[slot * 256 + 128 + tid] * invN - mean * mean;
            a  = gamma[tid] * rsqrtf(var + 1e-5f);
            cc = beta[tid] - mean * a;
        }
        bna[tid] = a; bnc[tid] = cc;
        b1s[tid] = mode ? gb1[tid] : 0.f;
        w2s[tid] = mode ? gW2[tid] : 0.f;
    }
    // retire the other slot (safe: its reader GEMM already completed; next writer SpMM not launched yet)
    if (zslot >= 0 && blockIdx.x == 0) g_stats[zslot * 256 + tid] = 0.f;

    // stage + split whole W: packed [kp][n], word = (k=2kp, k=2kp+1)
    for (int i = tid; i < 64 * 32; i += 256) {
        int kp = i >> 5, n4 = i & 31;
        float4 w0 = ((const float4*)(W + (2 * kp) * 128))[n4];
        float4 w1 = ((const float4*)(W + (2 * kp + 1) * 128))[n4];
        float e0[4] = {w0.x, w0.y, w0.z, w0.w};
        float e1[4] = {w1.x, w1.y, w1.z, w1.w};
        #pragma unroll
        for (int c = 0; c < 4; c++) {
            __nv_bfloat16 h0, l0, h1, l1;
            split_bf16(e0[c], h0, l0);
            split_bf16(e1[c], h1, l1);
            sWhi[kp * SWS + n4 * 4 + c] = pack2(h0, h1);
            sWlo[kp * SWS + n4 * 4 + c] = pack2(l0, l1);
        }
    }

    int rowbase = blockIdx.x * 128;
    int warp = tid >> 5, lane = tid & 31;
    int g = lane >> 2, t = lane & 3;
    int wm = warp >> 1, wn = warp & 1;
    int mbase = wm * 32;
    int nbase = wn * 64;

    // per-thread fixed staging assignment: 4 quads, row/kq constant across chunks
    int arow[4], akq[4];
    const float4* aptr[4];
    bool avalid[4];
    #pragma unroll
    for (int j = 0; j < 4; j++) {
        int idx = tid + j * 256;
        arow[j] = idx >> 3;
        akq[j]  = idx & 7;
        int gr = rowbase + arow[j];
        avalid[j] = gr < M;
        aptr[j] = (const float4*)(A + (size_t)(avalid[j] ? gr : 0) * HD) + akq[j];
    }
    float4 pref[4];
    #pragma unroll
    for (int j = 0; j < 4; j++)
        pref[j] = avalid[j] ? aptr[j][0] : make_float4(0.f, 0.f, 0.f, 0.f);

    float acc[2][8][4];
    #pragma unroll
    for (int i = 0; i < 2; i++)
        #pragma unroll
        for (int j = 0; j < 8; j++)
            #pragma unroll
            for (int c = 0; c < 4; c++) acc[i][j][c] = 0.f;

    #pragma unroll
    for (int c = 0; c < 4; c++) {
        int k0 = c * 32;
        __syncthreads();                       // packed buffers free (prev chunk's MMA done) / W+params ready
        // split prefetched chunk c -> packed smem (BN fused)
        #pragma unroll
        for (int j = 0; j < 4; j++) {
            int c0 = k0 + akq[j] * 4;
            float f0 = pref[j].x * bna[c0 + 0] + bnc[c0 + 0];
            float f1 = pref[j].y * bna[c0 + 1] + bnc[c0 + 1];
            float f2 = pref[j].z * bna[c0 + 2] + bnc[c0 + 2];
            float f3 = pref[j].w * bna[c0 + 3] + bnc[c0 + 3];
            __nv_bfloat16 h0, l0, h1, l1, h2, l2, h3, l3;
            split_bf16(f0, h0, l0);
            split_bf16(f1, h1, l1);
            split_bf16(f2, h2, l2);
            split_bf16(f3, h3, l3);
            int base = arow[j] * AST + akq[j] * 2;
            sAhi[base]     = pack2(h0, h1);
            sAhi[base + 1] = pack2(h2, h3);
            sAlo[base]     = pack2(l0, l1);
            sAlo[base + 1] = pack2(l2, l3);
        }
        __syncthreads();
        // issue prefetch for chunk c+1 (LDG latency hidden under the MMA block below)
        if (c < 3) {
            #pragma unroll
            for (int j = 0; j < 4; j++)
                pref[j] = avalid[j] ? aptr[j][(c + 1) * 8] : make_float4(0.f, 0.f, 0.f, 0.f);
        }
        #pragma unroll
        for (int ks2 = 0; ks2 < 2; ks2++) {
            int kpl = ks2 * 8;
            int kpg = (k0 >> 1) + kpl;
            uint32_t ahi[2][4], alo[2][4];
            #pragma unroll
            for (int i = 0; i < 2; i++) {
                int r0 = (mbase + i * 16 + g) * AST;
                int r8 = r0 + 8 * AST;
                ahi[i][0] = sAhi[r0 + kpl + t];     alo[i][0] = sAlo[r0 + kpl + t];
                ahi[i][1] = sAhi[r8 + kpl + t];     alo[i][1] = sAlo[r8 + kpl + t];
                ahi[i][2] = sAhi[r0 + kpl + t + 4]; alo[i][2] = sAlo[r0 + kpl + t + 4];
                ahi[i][3] = sAhi[r8 + kpl + t + 4]; alo[i][3] = sAlo[r8 + kpl + t + 4];
            }
            #pragma unroll
            for (int j = 0; j < 8; j++) {
                int n = nbase + j * 8 + g;
                uint32_t bh0 = sWhi[(kpg + t) * SWS + n];
                uint32_t bh1 = sWhi[(kpg + t + 4) * SWS + n];
                uint32_t bl0 = sWlo[(kpg + t) * SWS + n];
                uint32_t bl1 = sWlo[(kpg + t + 4) * SWS + n];
                #pragma unroll
                for (int i = 0; i < 2; i++) {
                    mma_bf16(acc[i][j], ahi[i], bh0, bh1);
                    mma_bf16(acc[i][j], ahi[i], bl0, bl1);
                    mma_bf16(acc[i][j], alo[i], bh0, bh1);
                }
            }
        }
    }

    if (mode == 0) {
        #pragma unroll
        for (int i = 0; i < 2; i++) {
            int r  = rowbase + mbase + i * 16 + g;
            int r8 = r + 8;
            #pragma unroll
            for (int j = 0; j < 8; j++) {
                int col = nbase + j * 8 + 2 * t;
                if (r < M)
                    *(float2*)(g_t + (size_t)r * HD + col) = make_float2(acc[i][j][0], acc[i][j][1]);
                if (r8 < M)
                    *(float2*)(g_t + (size_t)r8 * HD + col) = make_float2(acc[i][j][2], acc[i][j][3]);
            }
        }
    } else {
        __syncthreads();           // reuse sAhi as rsum[128][2]
        float* rsum = (float*)sAhi;
        #pragma unroll
        for (int i = 0; i < 2; i++) {
            float s0 = 0.f, s1 = 0.f;
            #pragma unroll
            for (int j = 0; j < 8; j++) {
                int col = nbase + j * 8 + 2 * t;
                s0 += fmaxf(acc[i][j][0] + b1s[col], 0.f)     * w2s[col];
                s0 += fmaxf(acc[i][j][1] + b1s[col + 1], 0.f) * w2s[col + 1];
                s1 += fmaxf(acc[i][j][2] + b1s[col], 0.f)     * w2s[col];
                s1 += fmaxf(acc[i][j][3] + b1s[col + 1], 0.f) * w2s[col + 1];
            }
            s0 += __shfl_xor_sync(0xffffffffu, s0, 1);
            s0 += __shfl_xor_sync(0xffffffffu, s0, 2);
            s1 += __shfl_xor_sync(0xffffffffu, s1, 1);
            s1 += __shfl_xor_sync(0xffffffffu, s1, 2);
            if (t == 0) {
                int lr = mbase + i * 16 + g;
                rsum[lr * 2 + wn]       = s0;
                rsum[(lr + 8) * 2 + wn] = s1;
            }
        }
        __syncthreads();
        if (tid < 128) {
            int row = rowbase + tid;
            if (row < M) {
                float z = rsum[tid * 2] + rsum[tid * 2 + 1] + gb2[0];
                g_gate[row] = 1.f / (1.f + expf(-z));
            }
        }
    }
}

// ---------------- SpMM: g_h = relu(A_hat*g_t + bias); fused BN stats into slot ----------------
__global__ void k_spmm(const float* __restrict__ bias, int N, int slot) {
    __shared__ __align__(16) float ssum[8 * 128];
    __shared__ __align__(16) float ssq[8 * 128];
    int warp = threadIdx.x >> 5, lane = threadIdx.x & 31;
    int v = blockIdx.x * 8 + warp;
    const int*   __restrict__ colp = (const int*)g_col;
    const float* __restrict__ wp   = (const float*)g_w;
    const float4* __restrict__ H4  = (const float4*)g_t;
    float4 acc = make_float4(0.f, 0.f, 0.f, 0.f);
    if (v < N) {
        int p = g_rowptr[v];
        int e = p + g_deg[v];
        for (; p + 3 < e; p += 4) {
            int s0 = colp[p], s1 = colp[p + 1], s2 = colp[p + 2], s3 = colp[p + 3];
            float w0 = wp[p], w1 = wp[p + 1], w2 = wp[p + 2], w3 = wp[p + 3];
            float4 h0 = H4[(size_t)s0 * 32 + lane];
            float4 h1 = H4[(size_t)s1 * 32 + lane];
            float4 h2 = H4[(size_t)s2 * 32 + lane];
            float4 h3 = H4[(size_t)s3 * 32 + lane];
            acc.x += w0 * h0.x + w1 * h1.x + w2 * h2.x + w3 * h3.x;
            acc.y += w0 * h0.y + w1 * h1.y + w2 * h2.y + w3 * h3.y;
            acc.z += w0 * h0.z + w1 * h1.z + w2 * h2.z + w3 * h3.z;
            acc.w += w0 * h0.w + w1 * h1.w + w2 * h2.w + w3 * h3.w;
        }
        for (; p < e; p++) {
            int s0 = colp[p]; float w0 = wp[p];
            float4 h0 = H4[(size_t)s0 * 32 + lane];
            acc.x += w0 * h0.x; acc.y += w0 * h0.y; acc.z += w0 * h0.z; acc.w += w0 * h0.w;
        }
        float di = g_dinv[v];
        float ws = di * di;
        float4 hs = H4[(size_t)v * 32 + lane];
        float4 b = ((const float4*)bias)[lane];
        acc.x = fmaxf(acc.x + ws * hs.x + b.x, 0.f);
        acc.y = fmaxf(acc.y + ws * hs.y + b.y, 0.f);
        acc.z = fmaxf(acc.z + ws * hs.z + b.z, 0.f);
        acc.w = fmaxf(acc.w + ws * hs.w + b.w, 0.f);
        ((float4*)g_h)[(size_t)v * 32 + lane] = acc;
    }
    if (slot >= 0) {
        int idx = warp * 128 + lane * 4;
        if (v >= N) acc = make_float4(0.f, 0.f, 0.f, 0.f);
        *(float4*)&ssum[idx] = acc;
        *(float4*)&ssq[idx] = make_float4(acc.x * acc.x, acc.y * acc.y, acc.z * acc.z, acc.w * acc.w);
        __syncthreads();
        int tid = threadIdx.x;
        if (tid < 128) {
            float s = 0.f, s2 = 0.f;
            #pragma unroll
            for (int w = 0; w < 8; w++) {
                s  += ssum[w * 128 + tid];
                s2 += ssq[w * 128 + tid];
            }
            atomicAdd(&g_stats[slot * 256 + tid], s);
            atomicAdd(&g_stats[slot * 256 + 128 + tid], s2);
        }
    }
}

// ---------------- gated pooling ----------------
__device__ __forceinline__ int lower_bound_i32(const int* a, int n, int key) {
    int lo = 0, hi = n;
    while (lo < hi) { int mid = (lo + hi) >> 1; if (a[mid] < key) lo = mid + 1; else hi = mid; }
    return lo;
}

__global__ void k_pool(const int* __restrict__ batch, int N) {
    int g = blockIdx.x;
    int col = threadIdx.x;
    int start = lower_bound_i32(batch, N, g);
    int end   = lower_bound_i32(batch, N, g + 1);
    float s = 0.f;
    for (int r = start; r < end; r++)
        s += g_h[(size_t)r * HD + col] * g_gate[r];
    g_pool[g * HD + col] = s;
}

__global__ void k_bnpool(const float* __restrict__ gamma, const float* __restrict__ beta) {
    int c = threadIdx.x;
    float s = 0.f, s2 = 0.f;
    for (int r = 0; r < NGRAPH; r++) {
        float v = g_pool[r * HD + c];
        s += v; s2 += v * v;
    }
    float invG = 1.f / (float)NGRAPH;
    float mean = s * invG;
    float var  = s2 * invG - mean * mean;
    float a = gamma[c] * rsqrtf(var + 1e-5f);
    g_stats2[c] = a;
    g_stats2[128 + c] = beta[c] - mean * a;
}

__global__ void k_fc(const float* __restrict__ fcW, const float* __restrict__ fcb) {
    int g = blockIdx.x, t = threadIdx.x;
    __shared__ float srow[128];
    srow[t] = g_pool[g * HD + t] * g_stats2[t] + g_stats2[128 + t];
    __syncthreads();
    float acc = fcb[t];
    #pragma unroll
    for (int k = 0; k < 128; k++)
        acc += srow[k] * fcW[k * 128 + t];
    g_g2[g * HD + t] = fmaxf(acc, 0.f);
}

__global__ void k_cls(const float* __restrict__ clsW, const float* __restrict__ clsb,
                      float* __restrict__ out) {
    int g = blockIdx.x, t = threadIdx.x;
    __shared__ float srow[128];
    __shared__ float lg[10];
    __shared__ float s_lse;
    for (int i = t; i < 128; i += 32) srow[i] = g_g2[g * HD + i];
    __syncthreads();
    if (t < 10) {
        float a = clsb[t];
        #pragma unroll
        for (int k = 0; k < 128; k++) a += srow[k] * clsW[k * 10 + t];
        lg[t] = a;
    }
    __syncthreads();
    if (t == 0) {
        float m = lg[0];
        #pragma unroll
        for (int i = 1; i < 10; i++) m = fmaxf(m, lg[i]);
        float s = 0.f;
        #pragma unroll
        for (int i = 0; i < 10; i++) s += expf(lg[i] - m);
        s_lse = m + logf(s);
    }
    __syncthreads();
    if (t < 10) out[g * 10 + t] = lg[t] - s_lse;
}

// ---------------- launch ----------------
extern "C" void kernel_launch(void* const* d_in, const int* in_sizes, int n_in,
                              void* d_out, int out_size) {
    const float* x           = (const float*)d_in[0];
    const int*   eidx        = (const int*)d_in[1];    // int32 (JAX x64 disabled)
    const int*   batch       = (const int*)d_in[2];
    const float* bn_feat_g   = (const float*)d_in[3];
    const float* bn_feat_b   = (const float*)d_in[4];
    const float* conv_feat_W = (const float*)d_in[5];
    const float* conv_feat_b = (const float*)d_in[6];
    const float* conv_W      = (const float*)d_in[7];
    const float* conv_b      = (const float*)d_in[8];
    const float* bn_conv_g   = (const float*)d_in[9];
    const float* bn_conv_b   = (const float*)d_in[10];
    const float* gate_W1     = (const float*)d_in[11];
    const float* gate_b1     = (const float*)d_in[12];
    const float* gate_W2     = (const float*)d_in[13];
    const float* gate_b2     = (const float*)d_in[14];
    const float* fc_W        = (const float*)d_in[15];
    const float* fc_b        = (const float*)d_in[16];
    const float* bn_fc_g     = (const float*)d_in[17];
    const float* bn_fc_b     = (const float*)d_in[18];
    const float* cls_W       = (const float*)d_in[19];
    const float* cls_b       = (const float*)d_in[20];
    float* out = (float*)d_out;

    int N = in_sizes[0] / HD;
    int E = in_sizes[1] / 2;
    int NB = (N + 1023) >> 10;
    int EB = (E + 255) / 256;
    int GB = (N + 127) / 128;
    int SB = (N + 7) / 8;
    float invN = 1.f / (float)N;

    static int smem_set = 0;
    int smem_bytes = SMEM_WORDS * 4;
    if (!smem_set) {
        cudaFuncSetAttribute(k_gemm_tc, cudaFuncAttributeMaxDynamicSharedMemorySize, smem_bytes);
        smem_set = 1;
    }

    // graph structure (CSR by counting sort)
    k_zero_deg<<<(N + 255) / 256, 256>>>(N);
    k_deg<<<EB, 256>>>(eidx, E);
    k_scan1<<<NB, 256>>>(N);
    k_scan2<<<1, 64>>>(NB);
    k_scan3<<<NB, 1024>>>(N);
    k_scatter<<<EB, 256>>>(eidx, E);

    // layer 0: stats(x) -> slot0; gemm reads slot0; spmm writes slot1
    k_colstats<<<1184, 128>>>(x, N);
    k_gemm_tc<<<GB, 256, smem_bytes>>>(x, 0, conv_feat_W, 0, -1, invN,
                                       bn_feat_g, bn_feat_b, 0, N, nullptr, nullptr, nullptr);
    k_spmm<<<SB, 256>>>(conv_feat_b, N, 1);

    // conv 1: reads slot1, zeroes slot0; spmm writes slot0
    k_gemm_tc<<<GB, 256, smem_bytes>>>(nullptr, 1, conv_W + 0 * 128 * 128, 1, 0, invN,
                                       bn_conv_g + 0, bn_conv_b + 0, 0, N, nullptr, nullptr, nullptr);
    k_spmm<<<SB, 256>>>(conv_b + 0, N, 0);

    // conv 2: reads slot0, zeroes slot1; spmm writes slot1
    k_gemm_tc<<<GB, 256, smem_bytes>>>(nullptr, 1, conv_W + 1 * 128 * 128, 0, 1, invN,
                                       bn_conv_g + 128, bn_conv_b + 128, 0, N, nullptr, nullptr, nullptr);
    k_spmm<<<SB, 256>>>(conv_b + 128, N, 1);

    // conv 3: reads slot1, zeroes slot0; spmm no stats
    k_gemm_tc<<<GB, 256, smem_bytes>>>(nullptr, 1, conv_W + 2 * 128 * 128, 1, 0, invN,
                                       bn_conv_g + 256, bn_conv_b + 256, 0, N, nullptr, nullptr, nullptr);
    k_spmm<<<SB, 256>>>(conv_b + 256, N, -1);

    // gate: no BN; zeroes slot1 (restores clean state for next replay)
    k_gemm_tc<<<GB, 256, smem_bytes>>>(nullptr, 1, gate_W1, -1, 1, invN,
                                       nullptr, nullptr, 1, N, gate_b1, gate_W2, gate_b2);

    // pooling + head
    k_pool<<<NGRAPH, 128>>>(batch, N);
    k_bnpool<<<1, 128>>>(bn_fc_g, bn_fc_b);
    k_fc<<<NGRAPH, 128>>>(fc_W, fc_b);
    k_cls<<<NGRAPH, 32>>>(cls_W, cls_b, out);
}

// round 12
// speedup vs baseline: 1.9086x; 1.1058x over previous
#include <cuda_runtime.h>
#include <cuda_bf16.h>
#include <cuda_fp16.h>
#include <math.h>
#include <stdint.h>

#define NMAX 50000
#define EMAX 600000
#define NGRAPH 256
#define HD 128

// ---------------- device scratch ----------------
__device__ __align__(16) int    g_deg[NMAX];
__device__ __align__(16) float  g_dinv[NMAX];
__device__ __align__(16) int    g_rowptr[NMAX];
__device__ __align__(16) int    g_cursor[NMAX];
__device__ __align__(16) int    g_col[EMAX];
__device__ __align__(16) float  g_w[EMAX];
__device__ __align__(16) float  g_h[NMAX * HD];
__device__ __align__(16) __half g_t16[NMAX * HD];   // GEMM output, fp16 (halves SpMM gather bytes)
__device__ __align__(16) float  g_gate[NMAX];
// two ping-pong stat slots: slot s -> sum at [s*256, +128), sumsq at [s*256+128, +128)
__device__ __align__(16) float  g_stats[512];
__device__ __align__(16) float  g_stats2[256];
__device__ __align__(16) float  g_pool[NGRAPH * HD];
__device__ __align__(16) int    g_part[128];

// ---------------- graph structure build ----------------
__global__ void k_zero_deg(int N) {
    int i = blockIdx.x * blockDim.x + threadIdx.x;
    if (i < N) g_deg[i] = 0;
}

__global__ void k_deg(const int* __restrict__ eidx, int E) {
    int e = blockIdx.x * blockDim.x + threadIdx.x;
    if (e < E) atomicAdd(&g_deg[eidx[E + e]], 1);
}

__global__ void k_scan1(int N) {   // per-1024-chunk sums -> g_part
    __shared__ int sh[256];
    int t = threadIdx.x;
    int base = blockIdx.x * 1024;
    int s = 0;
    #pragma unroll
    for (int j = 0; j < 4; j++) {
        int i = base + t + j * 256;
        if (i < N) s += g_deg[i];
    }
    sh[t] = s; __syncthreads();
    for (int off = 128; off > 0; off >>= 1) {
        if (t < off) sh[t] += sh[t + off];
        __syncthreads();
    }
    if (t == 0) g_part[blockIdx.x] = sh[0];
}

// scan3 now self-computes its partial base from raw g_part sums (k_scan2 eliminated)
__global__ void k_scan3(int N) {
    __shared__ int sh[1024];
    __shared__ int pb[64];
    __shared__ int pbase;
    int t = threadIdx.x;
    if (t < 64) pb[t] = (t < blockIdx.x) ? g_part[t] : 0;
    __syncthreads();
    if (t < 32) { pb[t] += pb[t + 32]; }
    __syncthreads();
    if (t == 0) {
        int acc = 0;
        #pragma unroll
        for (int i = 0; i < 32; i++) acc += pb[i];
        pbase = acc;
    }
    int i = blockIdx.x * 1024 + t;
    int v = (i < N) ? g_deg[i] : 0;
    __syncthreads();
    sh[t] = v; __syncthreads();
    for (int off = 1; off < 1024; off <<= 1) {
        int x = (t >= off) ? sh[t - off] : 0;
        __syncthreads();
        sh[t] += x;
        __syncthreads();
    }
    if (i < N) {
        int excl = sh[t] - v;
        int start = pbase + excl;
        g_rowptr[i] = start;
        g_cursor[i] = start;
        g_dinv[i] = rsqrtf((float)v + 1.0f);
    }
}

__global__ void k_scatter(const int* __restrict__ eidx, int E) {
    int e = blockIdx.x * blockDim.x + threadIdx.x;
    if (e < E) {
        int src = eidx[e];
        int dst = eidx[E + e];
        int pos = atomicAdd(&g_cursor[dst], 1);
        g_col[pos] = src;
        g_w[pos] = g_dinv[src] * g_dinv[dst];
    }
}

// ---------------- BN statistics for external input x (slot 0) ----------------
__global__ void k_colstats(const float* __restrict__ X, int N) {
    int col = threadIdx.x;  // 128
    float s = 0.f, s2 = 0.f;
    for (int r = blockIdx.x; r < N; r += gridDim.x) {
        float v = X[(size_t)r * HD + col];
        s += v; s2 += v * v;
    }
    atomicAdd(&g_stats[col], s);
    atomicAdd(&g_stats[128 + col], s2);
}

// ---------------- tensor-core GEMM (3xBF16 split, m16n8k16, reg-prefetch pipeline) ----------------
__device__ __forceinline__ void mma_bf16(float* c, const uint32_t* a, uint32_t b0, uint32_t b1) {
    asm volatile(
        "mma.sync.aligned.m16n8k16.row.col.f32.bf16.bf16.f32 "
        "{%0,%1,%2,%3}, {%4,%5,%6,%7}, {%8,%9}, {%0,%1,%2,%3};"
        : "+f"(c[0]), "+f"(c[1]), "+f"(c[2]), "+f"(c[3])
        : "r"(a[0]), "r"(a[1]), "r"(a[2]), "r"(a[3]), "r"(b0), "r"(b1));
}
__device__ __forceinline__ void split_bf16(float x, __nv_bfloat16& hi, __nv_bfloat16& lo) {
    hi = __float2bfloat16_rn(x);
    lo = __float2bfloat16_rn(x - __bfloat162float(hi));
}
__device__ __forceinline__ uint32_t pack2(__nv_bfloat16 e0, __nv_bfloat16 e1) {
    __nv_bfloat162 p(e0, e1);
    return *(uint32_t*)&p;
}

#define SWS 136
#define AST 20
#define SMEM_WORDS (2 * 64 * SWS + 2 * 128 * AST + 512)

// slot: BN stats slot to read (-1 = none). zslot: stats slot to zero (-1 = none).
// mode 0: write g_t16. mode 1: gate epilogue -> g_gate.
__global__ __launch_bounds__(256, 2) void k_gemm_tc(
    const float* __restrict__ Aext, int sel, const float* __restrict__ W,
    int slot, int zslot, float invN,
    const float* __restrict__ gamma, const float* __restrict__ beta,
    int mode, int M,
    const float* __restrict__ gb1, const float* __restrict__ gW2,
    const float* __restrict__ gb2)
{
    extern __shared__ uint32_t smw[];
    uint32_t* sWhi = smw;
    uint32_t* sWlo = sWhi + 64 * SWS;
    uint32_t* sAhi = sWlo + 64 * SWS;
    uint32_t* sAlo = sAhi + 128 * AST;
    float*    bna  = (float*)(sAlo + 128 * AST);
    float*    bnc  = bna + 128;
    float*    b1s  = bnc + 128;
    float*    w2s  = b1s + 128;

    const float* __restrict__ A = sel ? (const float*)g_h : Aext;
    int tid = threadIdx.x;

    if (tid < 128) {
        float a = 1.f, cc = 0.f;
        if (slot >= 0) {
            float mean = g_stats[slot * 256 + tid] * invN;
            float var  = g_stats[slot * 256 + 128 + tid] * invN - mean * mean;
            a  = gamma[tid] * rsqrtf(var + 1e-5f);
            cc = beta[tid] - mean * a;
        }
        bna[tid] = a; bnc[tid] = cc;
        b1s[tid] = mode ? gb1[tid] : 0.f;
        w2s[tid] = mode ? gW2[tid] : 0.f;
    }
    if (zslot >= 0 && blockIdx.x == 0) g_stats[zslot * 256 + tid] = 0.f;

    for (int i = tid; i < 64 * 32; i += 256) {
        int kp = i >> 5, n4 = i & 31;
        float4 w0 = ((const float4*)(W + (2 * kp) * 128))[n4];
        float4 w1 = ((const float4*)(W + (2 * kp + 1) * 128))[n4];
        float e0[4] = {w0.x, w0.y, w0.z, w0.w};
        float e1[4] = {w1.x, w1.y, w1.z, w1.w};
        #pragma unroll
        for (int c = 0; c < 4; c++) {
            __nv_bfloat16 h0, l0, h1, l1;
            split_bf16(e0[c], h0, l0);
            split_bf16(e1[c], h1, l1);
            sWhi[kp * SWS + n4 * 4 + c] = pack2(h0, h1);
            sWlo[kp * SWS + n4 * 4 + c] = pack2(l0, l1);
        }
    }

    int rowbase = blockIdx.x * 128;
    int warp = tid >> 5, lane = tid & 31;
    int g = lane >> 2, t = lane & 3;
    int wm = warp >> 1, wn = warp & 1;
    int mbase = wm * 32;
    int nbase = wn * 64;

    int arow[4], akq[4];
    const float4* aptr[4];
    bool avalid[4];
    #pragma unroll
    for (int j = 0; j < 4; j++) {
        int idx = tid + j * 256;
        arow[j] = idx >> 3;
        akq[j]  = idx & 7;
        int gr = rowbase + arow[j];
        avalid[j] = gr < M;
        aptr[j] = (const float4*)(A + (size_t)(avalid[j] ? gr : 0) * HD) + akq[j];
    }
    float4 pref[4];
    #pragma unroll
    for (int j = 0; j < 4; j++)
        pref[j] = avalid[j] ? aptr[j][0] : make_float4(0.f, 0.f, 0.f, 0.f);

    float acc[2][8][4];
    #pragma unroll
    for (int i = 0; i < 2; i++)
        #pragma unroll
        for (int j = 0; j < 8; j++)
            #pragma unroll
            for (int c = 0; c < 4; c++) acc[i][j][c] = 0.f;

    #pragma unroll
    for (int c = 0; c < 4; c++) {
        int k0 = c * 32;
        __syncthreads();
        #pragma unroll
        for (int j = 0; j < 4; j++) {
            int c0 = k0 + akq[j] * 4;
            float f0 = pref[j].x * bna[c0 + 0] + bnc[c0 + 0];
            float f1 = pref[j].y * bna[c0 + 1] + bnc[c0 + 1];
            float f2 = pref[j].z * bna[c0 + 2] + bnc[c0 + 2];
            float f3 = pref[j].w * bna[c0 + 3] + bnc[c0 + 3];
            __nv_bfloat16 h0, l0, h1, l1, h2, l2, h3, l3;
            split_bf16(f0, h0, l0);
            split_bf16(f1, h1, l1);
            split_bf16(f2, h2, l2);
            split_bf16(f3, h3, l3);
            int base = arow[j] * AST + akq[j] * 2;
            sAhi[base]     = pack2(h0, h1);
            sAhi[base + 1] = pack2(h2, h3);
            sAlo[base]     = pack2(l0, l1);
            sAlo[base + 1] = pack2(l2, l3);
        }
        __syncthreads();
        if (c < 3) {
            #pragma unroll
            for (int j = 0; j < 4; j++)
                pref[j] = avalid[j] ? aptr[j][(c + 1) * 8] : make_float4(0.f, 0.f, 0.f, 0.f);
        }
        #pragma unroll
        for (int ks2 = 0; ks2 < 2; ks2++) {
            int kpl = ks2 * 8;
            int kpg = (k0 >> 1) + kpl;
            uint32_t ahi[2][4], alo[2][4];
            #pragma unroll
            for (int i = 0; i < 2; i++) {
                int r0 = (mbase + i * 16 + g) * AST;
                int r8 = r0 + 8 * AST;
                ahi[i][0] = sAhi[r0 + kpl + t];     alo[i][0] = sAlo[r0 + kpl + t];
                ahi[i][1] = sAhi[r8 + kpl + t];     alo[i][1] = sAlo[r8 + kpl + t];
                ahi[i][2] = sAhi[r0 + kpl + t + 4]; alo[i][2] = sAlo[r0 + kpl + t + 4];
                ahi[i][3] = sAhi[r8 + kpl + t + 4]; alo[i][3] = sAlo[r8 + kpl + t + 4];
            }
            #pragma unroll
            for (int j = 0; j < 8; j++) {
                int n = nbase + j * 8 + g;
                uint32_t bh0 = sWhi[(kpg + t) * SWS + n];
                uint32_t bh1 = sWhi[(kpg + t + 4) * SWS + n];
                uint32_t bl0 = sWlo[(kpg + t) * SWS + n];
                uint32_t bl1 = sWlo[(kpg + t + 4) * SWS + n];
                #pragma unroll
                for (int i = 0; i < 2; i++) {
                    mma_bf16(acc[i][j], ahi[i], bh0, bh1);
                    mma_bf16(acc[i][j], ahi[i], bl0, bl1);
                    mma_bf16(acc[i][j], alo[i], bh0, bh1);
                }
            }
        }
    }

    if (mode == 0) {
        __half2* T2 = (__half2*)g_t16;
        #pragma unroll
        for (int i = 0; i < 2; i++) {
            int r  = rowbase + mbase + i * 16 + g;
            int r8 = r + 8;
            #pragma unroll
            for (int j = 0; j < 8; j++) {
                int col = nbase + j * 8 + 2 * t;
                if (r < M)
                    T2[((size_t)r * HD + col) >> 1] = __floats2half2_rn(acc[i][j][0], acc[i][j][1]);
                if (r8 < M)
                    T2[((size_t)r8 * HD + col) >> 1] = __floats2half2_rn(acc[i][j][2], acc[i][j][3]);
            }
        }
    } else {
        __syncthreads();
        float* rsum = (float*)sAhi;
        #pragma unroll
        for (int i = 0; i < 2; i++) {
            float s0 = 0.f, s1 = 0.f;
            #pragma unroll
            for (int j = 0; j < 8; j++) {
                int col = nbase + j * 8 + 2 * t;
                s0 += fmaxf(acc[i][j][0] + b1s[col], 0.f)     * w2s[col];
                s0 += fmaxf(acc[i][j][1] + b1s[col + 1], 0.f) * w2s[col + 1];
                s1 += fmaxf(acc[i][j][2] + b1s[col], 0.f)     * w2s[col];
                s1 += fmaxf(acc[i][j][3] + b1s[col + 1], 0.f) * w2s[col + 1];
            }
            s0 += __shfl_xor_sync(0xffffffffu, s0, 1);
            s0 += __shfl_xor_sync(0xffffffffu, s0, 2);
            s1 += __shfl_xor_sync(0xffffffffu, s1, 1);
            s1 += __shfl_xor_sync(0xffffffffu, s1, 2);
            if (t == 0) {
                int lr = mbase + i * 16 + g;
                rsum[lr * 2 + wn]       = s0;
                rsum[(lr + 8) * 2 + wn] = s1;
            }
        }
        __syncthreads();
        if (tid < 128) {
            int row = rowbase + tid;
            if (row < M) {
                float z = rsum[tid * 2] + rsum[tid * 2 + 1] + gb2[0];
                g_gate[row] = 1.f / (1.f + expf(-z));
            }
        }
    }
}

// ---------------- SpMM over fp16 features: g_h = relu(A_hat*t + bias); fused stats ----------------
__device__ __forceinline__ void acc_row(float4& acc, float w, uint2 raw) {
    float2 a = __half22float2(*(__half2*)&raw.x);
    float2 b = __half22float2(*(__half2*)&raw.y);
    acc.x += w * a.x; acc.y += w * a.y; acc.z += w * b.x; acc.w += w * b.y;
}

__global__ void k_spmm(const float* __restrict__ bias, int N, int slot) {
    __shared__ __align__(16) float ssum[8 * 128];
    __shared__ __align__(16) float ssq[8 * 128];
    int warp = threadIdx.x >> 5, lane = threadIdx.x & 31;
    int v = blockIdx.x * 8 + warp;
    const int*   __restrict__ colp = (const int*)g_col;
    const float* __restrict__ wp   = (const float*)g_w;
    const uint2* __restrict__ H2   = (const uint2*)g_t16;   // 8B = 4 halves per lane
    float4 acc = make_float4(0.f, 0.f, 0.f, 0.f);
    if (v < N) {
        int p = g_rowptr[v];
        int e = p + g_deg[v];
        for (; p + 3 < e; p += 4) {
            int s0 = colp[p], s1 = colp[p + 1], s2 = colp[p + 2], s3 = colp[p + 3];
            float w0 = wp[p], w1 = wp[p + 1], w2 = wp[p + 2], w3 = wp[p + 3];
            uint2 r0 = H2[(size_t)s0 * 32 + lane];
            uint2 r1 = H2[(size_t)s1 * 32 + lane];
            uint2 r2 = H2[(size_t)s2 * 32 + lane];
            uint2 r3 = H2[(size_t)s3 * 32 + lane];
            acc_row(acc, w0, r0);
            acc_row(acc, w1, r1);
            acc_row(acc, w2, r2);
            acc_row(acc, w3, r3);
        }
        for (; p < e; p++) {
            int s0 = colp[p]; float w0 = wp[p];
            uint2 r0 = H2[(size_t)s0 * 32 + lane];
            acc_row(acc, w0, r0);
        }
        float di = g_dinv[v];
        float ws = di * di;
        uint2 rs = H2[(size_t)v * 32 + lane];
        acc_row(acc, ws, rs);
        float4 b = ((const float4*)bias)[lane];
        acc.x = fmaxf(acc.x + b.x, 0.f);
        acc.y = fmaxf(acc.y + b.y, 0.f);
        acc.z = fmaxf(acc.z + b.z, 0.f);
        acc.w = fmaxf(acc.w + b.w, 0.f);
        ((float4*)g_h)[(size_t)v * 32 + lane] = acc;
    }
    if (slot >= 0) {
        int idx = warp * 128 + lane * 4;
        if (v >= N) acc = make_float4(0.f, 0.f, 0.f, 0.f);
        *(float4*)&ssum[idx] = acc;
        *(float4*)&ssq[idx] = make_float4(acc.x * acc.x, acc.y * acc.y, acc.z * acc.z, acc.w * acc.w);
        __syncthreads();
        int tid = threadIdx.x;
        if (tid < 128) {
            float s = 0.f, s2 = 0.f;
            #pragma unroll
            for (int w = 0; w < 8; w++) {
                s  += ssum[w * 128 + tid];
                s2 += ssq[w * 128 + tid];
            }
            atomicAdd(&g_stats[slot * 256 + tid], s);
            atomicAdd(&g_stats[slot * 256 + 128 + tid], s2);
        }
    }
}

// ---------------- gated pooling + head ----------------
__device__ __forceinline__ int lower_bound_i32(const int* a, int n, int key) {
    int lo = 0, hi = n;
    while (lo < hi) { int mid = (lo + hi) >> 1; if (a[mid] < key) lo = mid + 1; else hi = mid; }
    return lo;
}

__global__ void k_pool(const int* __restrict__ batch, int N) {
    int g = blockIdx.x;
    int col = threadIdx.x;
    int start = lower_bound_i32(batch, N, g);
    int end   = lower_bound_i32(batch, N, g + 1);
    float s = 0.f;
    for (int r = start; r < end; r++)
        s += g_h[(size_t)r * HD + col] * g_gate[r];
    g_pool[g * HD + col] = s;
}

__global__ void k_bnpool(const float* __restrict__ gamma, const float* __restrict__ beta) {
    int c = threadIdx.x;
    float s = 0.f, s2 = 0.f;
    for (int r = 0; r < NGRAPH; r++) {
        float v = g_pool[r * HD + c];
        s += v; s2 += v * v;
    }
    float invG = 1.f / (float)NGRAPH;
    float mean = s * invG;
    float var  = s2 * invG - mean * mean;
    float a = gamma[c] * rsqrtf(var + 1e-5f);
    g_stats2[c] = a;
    g_stats2[128 + c] = beta[c] - mean * a;
}

// fused FC + classifier + log_softmax: 256 blocks x 128 threads, g2 row stays in smem
__global__ void k_fccls(const float* __restrict__ fcW, const float* __restrict__ fcb,
                        const float* __restrict__ clsW, const float* __restrict__ clsb,
                        float* __restrict__ out) {
    int g = blockIdx.x, t = threadIdx.x;
    __shared__ float srow[128];
    __shared__ float srow2[128];
    __shared__ float lg[10];
    __shared__ float s_lse;
    srow[t] = g_pool[g * HD + t] * g_stats2[t] + g_stats2[128 + t];
    __syncthreads();
    float acc = fcb[t];
    #pragma unroll
    for (int k = 0; k < 128; k++)
        acc += srow[k] * fcW[k * 128 + t];
    srow2[t] = fmaxf(acc, 0.f);
    __syncthreads();
    if (t < 10) {
        float a = clsb[t];
        #pragma unroll
        for (int k = 0; k < 128; k++) a += srow2[k] * clsW[k * 10 + t];
        lg[t] = a;
    }
    __syncthreads();
    if (t == 0) {
        float m = lg[0];
        #pragma unroll
        for (int i = 1; i < 10; i++) m = fmaxf(m, lg[i]);
        float s = 0.f;
        #pragma unroll
        for (int i = 0; i < 10; i++) s += expf(lg[i] - m);
        s_lse = m + logf(s);
    }
    __syncthreads();
    if (t < 10) out[g * 10 + t] = lg[t] - s_lse;
}

// ---------------- launch ----------------
extern "C" void kernel_launch(void* const* d_in, const int* in_sizes, int n_in,
                              void* d_out, int out_size) {
    const float* x           = (const float*)d_in[0];
    const int*   eidx        = (const int*)d_in[1];    // int32 (JAX x64 disabled)
    const int*   batch       = (const int*)d_in[2];
    const float* bn_feat_g   = (const float*)d_in[3];
    const float* bn_feat_b   = (const float*)d_in[4];
    const float* conv_feat_W = (const float*)d_in[5];
    const float* conv_feat_b = (const float*)d_in[6];
    const float* conv_W      = (const float*)d_in[7];
    const float* conv_b      = (const float*)d_in[8];
    const float* bn_conv_g   = (const float*)d_in[9];
    const float* bn_conv_b   = (const float*)d_in[10];
    const float* gate_W1     = (const float*)d_in[11];
    const float* gate_b1     = (const float*)d_in[12];
    const float* gate_W2     = (const float*)d_in[13];
    const float* gate_b2     = (const float*)d_in[14];
    const float* fc_W        = (const float*)d_in[15];
    const float* fc_b        = (const float*)d_in[16];
    const float* bn_fc_g     = (const float*)d_in[17];
    const float* bn_fc_b     = (const float*)d_in[18];
    const float* cls_W       = (const float*)d_in[19];
    const float* cls_b       = (const float*)d_in[20];
    float* out = (float*)d_out;

    int N = in_sizes[0] / HD;
    int E = in_sizes[1] / 2;
    int NB = (N + 1023) >> 10;
    int EB = (E + 255) / 256;
    int GB = (N + 127) / 128;
    int SB = (N + 7) / 8;
    float invN = 1.f / (float)N;

    static int smem_set = 0;
    int smem_bytes = SMEM_WORDS * 4;
    if (!smem_set) {
        cudaFuncSetAttribute(k_gemm_tc, cudaFuncAttributeMaxDynamicSharedMemorySize, smem_bytes);
        smem_set = 1;
    }

    // graph structure (CSR by counting sort)
    k_zero_deg<<<(N + 255) / 256, 256>>>(N);
    k_deg<<<EB, 256>>>(eidx, E);
    k_scan1<<<NB, 256>>>(N);
    k_scan3<<<NB, 1024>>>(N);
    k_scatter<<<EB, 256>>>(eidx, E);

    // layer 0: stats(x) -> slot0; gemm reads slot0; spmm writes slot1
    k_colstats<<<1184, 128>>>(x, N);
    k_gemm_tc<<<GB, 256, smem_bytes>>>(x, 0, conv_feat_W, 0, -1, invN,
                                       bn_feat_g, bn_feat_b, 0, N, nullptr, nullptr, nullptr);
    k_spmm<<<SB, 256>>>(conv_feat_b, N, 1);

    // conv 1: reads slot1, zeroes slot0; spmm writes slot0
    k_gemm_tc<<<GB, 256, smem_bytes>>>(nullptr, 1, conv_W + 0 * 128 * 128, 1, 0, invN,
                                       bn_conv_g + 0, bn_conv_b + 0, 0, N, nullptr, nullptr, nullptr);
    k_spmm<<<SB, 256>>>(conv_b + 0, N, 0);

    // conv 2: reads slot0, zeroes slot1; spmm writes slot1
    k_gemm_tc<<<GB, 256, smem_bytes>>>(nullptr, 1, conv_W + 1 * 128 * 128, 0, 1, invN,
                                       bn_conv_g + 128, bn_conv_b + 128, 0, N, nullptr, nullptr, nullptr);
    k_spmm<<<SB, 256>>>(conv_b + 128, N, 1);

    // conv 3: reads slot1, zeroes slot0; spmm no stats
    k_gemm_tc<<<GB, 256, smem_bytes>>>(nullptr, 1, conv_W + 2 * 128 * 128, 1, 0, invN,
                                       bn_conv_g + 256, bn_conv_b + 256, 0, N, nullptr, nullptr, nullptr);
    k_spmm<<<SB, 256>>>(conv_b + 256, N, -1);

    // gate: no BN; zeroes slot1 (restores clean state for next replay)
    k_gemm_tc<<<GB, 256, smem_bytes>>>(nullptr, 1, gate_W1, -1, 1, invN,
                                       nullptr, nullptr, 1, N, gate_b1, gate_W2, gate_b2);

    // pooling + head
    k_pool<<<NGRAPH, 128>>>(batch, N);
    k_bnpool<<<1, 128>>>(bn_fc_g, bn_fc_b);
    k_fccls<<<NGRAPH, 128>>>(fc_W, fc_b, cls_W, cls_b, out);
}